// round 11
// baseline (speedup 1.0000x reference)
#include <cuda_runtime.h>
#include <cuda_fp16.h>
#include <cstdint>
#include <math.h>

// ---------------- problem constants ----------------
#define SEQ     2048
#define BATCH   2
#define RTOT    4096      // BATCH*SEQ
#define DMODEL  1024
#define D1      2048
#define NHEAD   16
#define HDIM    128
#define NKP     16
#define RANKC   32
#define GAMMA_F 0.999f
#define NSEG    15
#define LNIG    0.0010005003335835335f   // -ln(0.999)

__constant__ int c_OFF[NSEG] = {1,138,274,411,547,683,820,956,1093,1229,1365,1502,1638,1775,1911};

// ---------------- device-global scratch (NEVER passed from host) ----------------
__device__ __align__(128) float g_Ut[(size_t)D1 * RTOT]; // U^T  [c][m]
__device__ __align__(128) float g_Vt[(size_t)D1 * RTOT]; // V^T  [c][m]
__device__ __align__(128) float g_Gt[(size_t)D1 * RTOT]; // gated [c][m]
__device__ __align__(128) float g_CE [NSEG * D1];
__device__ __align__(128) float g_CF [NSEG * D1];
__device__ __align__(128) float g_CEn[NSEG * D1];
__device__ __align__(128) float g_CFn[NSEG * D1];
// split-precision fp16 planes
__device__ __align__(128) __half g_xh [(size_t)RTOT * DMODEL];
__device__ __align__(128) __half g_xl [(size_t)RTOT * DMODEL];
__device__ __align__(128) __half g_Wth[(size_t)D1 * DMODEL];
__device__ __align__(128) __half g_Ath[(size_t)RTOT * D1];
__device__ __align__(128) __half g_Atl[(size_t)RTOT * D1];

// ---------------- helpers ----------------
__device__ __forceinline__ uint32_t smem_to_u32(const void* p) {
    uint32_t a;
    asm("{ .reg .u64 t; cvta.to.shared.u64 t, %1; cvt.u32.u64 %0, t; }" : "=r"(a) : "l"(p));
    return a;
}
#define SMEM_SW64(o) ((o) ^ (((o) >> 3) & 0x30))
__device__ __forceinline__ float silu_f(float x) { return x / (1.0f + expf(-x)); }

#define LDM4(r, addr) \
    asm volatile("ldmatrix.sync.aligned.m8n8.x4.shared.b16 {%0,%1,%2,%3}, [%4];" \
        : "=r"((r)[0]), "=r"((r)[1]), "=r"((r)[2]), "=r"((r)[3]) : "r"(addr))
#define MMA16816(c, a, b0, b1) \
    asm volatile("mma.sync.aligned.m16n8k16.row.col.f32.f16.f16.f32 " \
        "{%0,%1,%2,%3}, {%4,%5,%6,%7}, {%8,%9}, {%0,%1,%2,%3};" \
        : "+f"((c)[0]), "+f"((c)[1]), "+f"((c)[2]), "+f"((c)[3]) \
        : "r"((a)[0]), "r"((a)[1]), "r"((a)[2]), "r"((a)[3]), "r"(b0), "r"(b1))
#define CP16(dst, src) \
    asm volatile("cp.async.cg.shared.global [%0], [%1], 16;" :: "r"(dst), "l"(src) : "memory")
#define CP_COMMIT()  asm volatile("cp.async.commit_group;" ::: "memory")
#define CP_WAIT1()   asm volatile("cp.async.wait_group 1;" ::: "memory")
#define CP_WAIT0()   asm volatile("cp.async.wait_group 0;" ::: "memory")

// ---------------- coefficient kernel ----------------
__global__ void coef_kernel(const float* __restrict__ a_pos, const float* __restrict__ b_pos,
                            const float* __restrict__ a_neg, const float* __restrict__ b_neg)
{
    int h = blockIdx.x;
    int d = threadIdx.x;
    bool neg = (blockIdx.y != 0);
    const float* A  = neg ? a_neg : a_pos;
    const float* Bm = neg ? b_neg : b_pos;
    float* CE = neg ? g_CEn : g_CE;
    float* CF = neg ? g_CFn : g_CF;

    __shared__ float sa[NKP][RANKC];
    for (int i = threadIdx.x; i < NKP * RANKC; i += 128)
        sa[i / RANKC][i % RANKC] = A[h * NKP * RANKC + i];
    __syncthreads();

    float br[RANKC];
#pragma unroll
    for (int r = 0; r < RANKC; r++)
        br[r] = Bm[((size_t)h * RANKC + r) * HDIM + d];

    float kind[NKP];
#pragma unroll
    for (int k = 0; k < NKP; k++) {
        float s = 0.f;
#pragma unroll
        for (int r = 0; r < RANKC; r++) s += sa[k][r] * br[r];
        kind[k] = s;
    }

    const float cm = 15.0f / 2046.0f;
    int c = h * HDIM + d;
    float Pp = 0.f, Qp = 0.f;
#pragma unroll
    for (int j = 0; j < NSEG; j++) {
        float D = kind[j + 1] - kind[j];
        float P = kind[j] - (cm + (float)j) * D;
        float Q = cm * D;
        int O = c_OFF[j];
        float gp = (float)pow((double)0.999, (double)O);
        CE[j * D1 + c] = gp * ((P - Pp) + (Q - Qp) * (float)O);
        CF[j * D1 + c] = gp * (Q - Qp);
        Pp = P; Qp = Q;
    }
}

// ---------------- x -> fp16 hi/lo ----------------
__global__ __launch_bounds__(256)
void convert_split_x(const float* __restrict__ src)
{
    __half* dh = g_xh;
    __half* dl = g_xl;
    int i = blockIdx.x * blockDim.x + threadIdx.x;
    float4 v = ((const float4*)src)[i];
    float vv[4] = {v.x, v.y, v.z, v.w};
    __half h[4], l[4];
#pragma unroll
    for (int j = 0; j < 4; j++) {
        h[j] = __float2half_rn(vv[j]);
        l[j] = __float2half_rn(vv[j] - __half2float(h[j]));
    }
    ((__half2*)dh)[2*i]   = __halves2half2(h[0], h[1]);
    ((__half2*)dh)[2*i+1] = __halves2half2(h[2], h[3]);
    ((__half2*)dl)[2*i]   = __halves2half2(l[0], l[1]);
    ((__half2*)dl)[2*i+1] = __halves2half2(l[2], l[3]);
}

// transpose fp32 [R][C] -> fp16 [C][R]; optionally also lo-plane.
__global__ __launch_bounds__(256)
void transpose_split(const float* __restrict__ src_ext, int R, int C,
                     int src_is_gt, int dst_sel)
{
    const float* src = src_is_gt ? g_Gt : src_ext;
    __half* dh = dst_sel ? g_Ath : g_Wth;
    __half* dl = g_Atl;

    __shared__ float tile[32][33];
    int c0 = blockIdx.x * 32, r0 = blockIdx.y * 32;
    int tx = threadIdx.x & 31, ty = threadIdx.x >> 5;  // (32,8)
#pragma unroll
    for (int j = 0; j < 4; j++)
        tile[ty + 8 * j][tx] = src[(size_t)(r0 + ty + 8 * j) * C + c0 + tx];
    __syncthreads();
#pragma unroll
    for (int j = 0; j < 4; j++) {
        float v = tile[tx][ty + 8 * j];
        size_t o = (size_t)(c0 + ty + 8 * j) * R + r0 + tx;
        __half h = __float2half_rn(v);
        dh[o] = h;
        if (dst_sel) dl[o] = __float2half_rn(v - __half2float(h));
    }
}

// ---------------- GEMM common pieces ----------------
#define GM_KC    32
#define ST_AH    0
#define ST_AL    8192
#define ST_BH    16384
#define STAGE_SZ 24576
#define GEMM2S_SMEM (2 * STAGE_SZ)
#define GEMM3S_SMEM (3 * STAGE_SZ)

// one chunk's MMAs from stage base 'st' — RAW-chain-free ordering:
// all 16 aH MMAs (independent accs), then all 16 aL MMAs (reuse dist = 16)
#define GEMM_COMPUTE_CHUNK(st)                                                        \
    _Pragma("unroll")                                                                 \
    for (int ks = 0; ks < 2; ks++) {                                                  \
        uint32_t aH[4][4], aL[4][4];                                                  \
        _Pragma("unroll")                                                             \
        for (int mt = 0; mt < 4; mt++) {                                              \
            int m = wm * 64 + mt * 16 + a_r;                                          \
            uint32_t off = SMEM_SW64((uint32_t)(m * 64 + ks * 32 + a_c));             \
            LDM4(aH[mt], (st) + ST_AH + off);                                         \
            LDM4(aL[mt], (st) + ST_AL + off);                                         \
        }                                                                             \
        uint32_t bH0[4], bH1[4];                                                      \
        {                                                                             \
            int n = wn * 32 + b_r;                                                    \
            uint32_t off = SMEM_SW64((uint32_t)(n * 64 + ks * 32 + b_c));             \
            LDM4(bH0, (st) + ST_BH + off);                                            \
            int n2 = wn * 32 + 16 + b_r;                                              \
            uint32_t off2 = SMEM_SW64((uint32_t)(n2 * 64 + ks * 32 + b_c));           \
            LDM4(bH1, (st) + ST_BH + off2);                                           \
        }                                                                             \
        _Pragma("unroll")                                                             \
        for (int mt = 0; mt < 4; mt++) {                                              \
            MMA16816(acc[mt][0], aH[mt], bH0[0], bH0[1]);                             \
            MMA16816(acc[mt][1], aH[mt], bH0[2], bH0[3]);                             \
            MMA16816(acc[mt][2], aH[mt], bH1[0], bH1[1]);                             \
            MMA16816(acc[mt][3], aH[mt], bH1[2], bH1[3]);                             \
        }                                                                             \
        _Pragma("unroll")                                                             \
        for (int mt = 0; mt < 4; mt++) {                                              \
            MMA16816(acc[mt][0], aL[mt], bH0[0], bH0[1]);                             \
            MMA16816(acc[mt][1], aL[mt], bH0[2], bH0[3]);                             \
            MMA16816(acc[mt][2], aL[mt], bH1[0], bH1[1]);                             \
            MMA16816(acc[mt][3], aL[mt], bH1[2], bH1[3]);                             \
        }                                                                             \
    }

#define GEMM_PROLOGUE()                                                               \
    const __half* Ah = a_sel ? g_Ath : g_xh;                                          \
    const __half* Al = a_sel ? g_Atl : g_xl;                                          \
    const __half* Bh = g_Wth;                                                         \
    float* Cout = (mode == 1) ? ext_out : (c_sel ? g_Vt : g_Ut);                      \
    extern __shared__ char dsm[];                                                     \
    uint32_t sbase = smem_to_u32(dsm);                                                \
    int tid = threadIdx.x;                                                            \
    int wid = tid >> 5, lane = tid & 31;                                              \
    int m0 = blockIdx.x * 128, n0 = blockIdx.y * 128;                                 \
    int wm = wid & 1;                                                                 \
    int wn = wid >> 1;                                                                \
    int a_r = (lane & 7) + ((lane >> 3) & 1) * 8;                                     \
    int a_c = (lane >> 4) * 16;                                                       \
    int b_r = (lane & 7) + ((lane >> 4) & 1) * 8;                                     \
    int b_c = ((lane >> 3) & 1) * 16;                                                 \
    float acc[4][4][4];                                                               \
    _Pragma("unroll")                                                                 \
    for (int i = 0; i < 4; i++)                                                       \
        _Pragma("unroll")                                                             \
        for (int j = 0; j < 4; j++)                                                   \
            _Pragma("unroll")                                                         \
            for (int q = 0; q < 4; q++) acc[i][j][q] = 0.f;                           \
    const __half* pAH = Ah + (size_t)m0 * Ktot;                                       \
    const __half* pAL = Al + (size_t)m0 * Ktot;                                       \
    const __half* pBH = Bh + (size_t)n0 * Ktot;                                       \
    int sa_row = tid >> 2, sa_seg = tid & 3;                                          \
    uint32_t sa_off  = SMEM_SW64((uint32_t)(sa_row * 64 + sa_seg * 16));              \
    uint32_t sa_off2 = SMEM_SW64((uint32_t)((sa_row + 64) * 64 + sa_seg * 16));       \
    int nkc = Ktot / GM_KC;                                                           \
    auto load_chunk = [&](int kc, int s) {                                            \
        int k0 = kc * GM_KC;                                                          \
        uint32_t st = sbase + s * STAGE_SZ;                                           \
        CP16(st + ST_AH + sa_off,  pAH + (size_t)sa_row * Ktot + k0 + sa_seg * 8);    \
        CP16(st + ST_AH + sa_off2, pAH + (size_t)(sa_row + 64) * Ktot + k0 + sa_seg * 8); \
        CP16(st + ST_AL + sa_off,  pAL + (size_t)sa_row * Ktot + k0 + sa_seg * 8);    \
        CP16(st + ST_AL + sa_off2, pAL + (size_t)(sa_row + 64) * Ktot + k0 + sa_seg * 8); \
        CP16(st + ST_BH + sa_off,  pBH + (size_t)sa_row * Ktot + k0 + sa_seg * 8);    \
        CP16(st + ST_BH + sa_off2, pBH + (size_t)(sa_row + 64) * Ktot + k0 + sa_seg * 8); \
    };

#define GEMM_EPILOGUE()                                                               \
    int er = lane >> 2, ec = (lane & 3) * 2;                                          \
    _Pragma("unroll")                                                                 \
    for (int mt = 0; mt < 4; mt++) {                                                  \
        _Pragma("unroll")                                                             \
        for (int nt = 0; nt < 4; nt++) {                                              \
            int mA = m0 + wm * 64 + mt * 16 + er;                                     \
            int nA = n0 + wn * 32 + nt * 8 + ec;                                      \
            float b0 = bias[nA], b1 = bias[nA + 1];                                   \
            float* c = acc[mt][nt];                                                   \
            if (mode == 0) {                                                          \
                Cout[(size_t)nA * strideC + mA]           = silu_f(c[0] + b0);        \
                Cout[(size_t)(nA + 1) * strideC + mA]     = silu_f(c[1] + b1);        \
                Cout[(size_t)nA * strideC + mA + 8]       = silu_f(c[2] + b0);        \
                Cout[(size_t)(nA + 1) * strideC + mA + 8] = silu_f(c[3] + b1);        \
            } else {                                                                  \
                Cout[(size_t)mA * strideC + nA]           = c[0] + b0;                \
                Cout[(size_t)mA * strideC + nA + 1]       = c[1] + b1;                \
                Cout[(size_t)(mA + 8) * strideC + nA]     = c[2] + b0;                \
                Cout[(size_t)(mA + 8) * strideC + nA + 1] = c[3] + b1;                \
            }                                                                         \
        }                                                                             \
    }

// ---- 2-stage (48KB, no opt-in) fallback ----
__global__ __launch_bounds__(256, 2)
void gemm_f16_split2(const float* __restrict__ bias, float* __restrict__ ext_out,
                     int Ktot, int strideC, int mode, int a_sel, int c_sel)
{
    GEMM_PROLOGUE()
    load_chunk(0, 0);
    CP_COMMIT();
    for (int kc = 0; kc < nkc; kc++) {
        int s = kc & 1;
        if (kc + 1 < nkc) {
            load_chunk(kc + 1, s ^ 1);
            CP_COMMIT();
            CP_WAIT1();
        } else {
            CP_WAIT0();
        }
        __syncthreads();
        uint32_t st = sbase + s * STAGE_SZ;
        GEMM_COMPUTE_CHUNK(st)
        __syncthreads();
    }
    GEMM_EPILOGUE()
}

// ---- 3-stage (72KB, opt-in), single barrier per chunk ----
__global__ __launch_bounds__(256, 2)
void gemm_f16_split3(const float* __restrict__ bias, float* __restrict__ ext_out,
                     int Ktot, int strideC, int mode, int a_sel, int c_sel)
{
    GEMM_PROLOGUE()
    load_chunk(0, 0);
    CP_COMMIT();
    load_chunk(1, 1);
    CP_COMMIT();
    for (int kc = 0; kc < nkc; kc++) {
        if (kc + 1 < nkc) CP_WAIT1(); else CP_WAIT0();
        __syncthreads();
        if (kc + 2 < nkc) {
            int sN = kc + 2 - ((kc + 2) / 3) * 3;
            load_chunk(kc + 2, sN);
            CP_COMMIT();
        }
        int s = kc - (kc / 3) * 3;
        uint32_t st = sbase + s * STAGE_SZ;
        GEMM_COMPUTE_CHUNK(st)
    }
    GEMM_EPILOGUE()
}

// ---------------- fused scan + combine (prefix-sum formulation) ----------------
// e_t = g^t * W_t ;  f_t = g^t * (t*W_{t-1} - X_{t-1})   [W,X prefix sums of v*g^-s, s*v*g^-s]
// g_t = g^-t * (TW2 - W2_{t-1}) ; h_t = g^-t * ((TX2 - X2_t) - t*(TW2 - W2_t))
__global__ __launch_bounds__(256)
void scan_combine_kernel(const float* __restrict__ t_zero)
{
    int c = blockIdx.x >> 1;
    int b = blockIdx.x & 1;
    size_t base = (size_t)c * RTOT + (size_t)b * SEQ;

    __shared__ float sv[SEQ], se[SEQ], sf[SEQ], sg[SEQ], sh2[SEQ];
    __shared__ float sWT[8][4];
    __shared__ float sCE[NSEG], sCF[NSEG], sCEn[NSEG], sCFn[NSEG];

    int tid = threadIdx.x;
    int lane = tid & 31, wrp = tid >> 5;

    // load 8 contiguous elements
    float4 v0 = ((const float4*)(g_Vt + base))[tid * 2];
    float4 v1 = ((const float4*)(g_Vt + base))[tid * 2 + 1];
    float v[8] = {v0.x, v0.y, v0.z, v0.w, v1.x, v1.y, v1.z, v1.w};
    ((float4*)sv)[tid * 2]     = v0;
    ((float4*)sv)[tid * 2 + 1] = v1;

    if (tid < NSEG) {
        sCE [tid] = g_CE [tid * D1 + c];
        sCF [tid] = g_CF [tid * D1 + c];
        sCEn[tid] = g_CEn[tid * D1 + c];
        sCFn[tid] = g_CFn[tid * D1 + c];
    }
    float tz = t_zero[c];

    // pass A: per-thread totals of (w, x, w2, x2)
    int s0 = tid * 8;
    float tW = 0.f, tX = 0.f, tW2 = 0.f, tX2 = 0.f;
#pragma unroll
    for (int i = 0; i < 8; i++) {
        float s = (float)(s0 + i);
        float gim = __expf(s * LNIG);    // gamma^-s
        float gp  = __expf(-s * LNIG);   // gamma^+s
        float w  = v[i] * gim, x  = s * w;
        float w2 = v[i] * gp,  x2 = s * w2;
        tW += w; tX += x; tW2 += w2; tX2 += x2;
    }
    // warp inclusive scan (4-wide)
    float iW = tW, iX = tX, iW2 = tW2, iX2 = tX2;
#pragma unroll
    for (int d = 1; d < 32; d <<= 1) {
        float aW  = __shfl_up_sync(0xffffffffu, iW,  d);
        float aX  = __shfl_up_sync(0xffffffffu, iX,  d);
        float aW2 = __shfl_up_sync(0xffffffffu, iW2, d);
        float aX2 = __shfl_up_sync(0xffffffffu, iX2, d);
        if (lane >= d) { iW += aW; iX += aX; iW2 += aW2; iX2 += aX2; }
    }
    if (lane == 31) {
        sWT[wrp][0] = iW; sWT[wrp][1] = iX; sWT[wrp][2] = iW2; sWT[wrp][3] = iX2;
    }
    __syncthreads();
    float bW = 0.f, bX = 0.f, bW2 = 0.f, bX2 = 0.f;
    float TW = 0.f, TX = 0.f, TW2 = 0.f, TX2 = 0.f;
#pragma unroll
    for (int w8 = 0; w8 < 8; w8++) {
        float a0 = sWT[w8][0], a1 = sWT[w8][1], a2 = sWT[w8][2], a3 = sWT[w8][3];
        if (w8 < wrp) { bW += a0; bX += a1; bW2 += a2; bX2 += a3; }
        TW += a0; TX += a1; TW2 += a2; TX2 += a3;
    }
    // exclusive running prefixes at thread start
    float PW = bW + iW - tW, PX = bX + iX - tX;
    float PW2 = bW2 + iW2 - tW2, PX2 = bX2 + iX2 - tX2;

    // pass B: per-element outputs
#pragma unroll
    for (int i = 0; i < 8; i++) {
        float s = (float)(s0 + i);
        float gim = __expf(s * LNIG);
        float gp  = __expf(-s * LNIG);
        float w  = v[i] * gim, x  = s * w;
        float w2 = v[i] * gp,  x2 = s * w2;
        PW += w; PX += x; PW2 += w2; PX2 += x2;   // inclusive at s
        int t = s0 + i;
        se[t]  = gp * PW;
        sf[t]  = gp * (s * (PW - w) - (PX - x));
        sg[t]  = gim * (TW2 - PW2 + w2);
        sh2[t] = gim * ((TX2 - PX2) - s * (TW2 - PW2));
    }
    __syncthreads();

    // combine
#pragma unroll
    for (int rpt = 0; rpt < 8; rpt++) {
        int t = tid + rpt * 256;
        float acc = tz * sv[t];
#pragma unroll
        for (int m = 0; m < NSEG; m++) {
            int o = c_OFF[m];
            int tm = t - o;
            if (tm >= 0)  acc += sCE[m]  * se[tm] + sCF[m]  * sf[tm];
            int tp = t + o;
            if (tp < SEQ) acc += sCEn[m] * sg[tp] + sCFn[m] * sh2[tp];
        }
        float uu = g_Ut[base + t];
        g_Gt[base + t] = acc * uu;
    }
}

// ---------------- launch ----------------
extern "C" void kernel_launch(void* const* d_in, const int* in_sizes, int n_in,
                              void* d_out, int out_size)
{
    (void)in_sizes; (void)n_in; (void)out_size;
    const float* x      = (const float*)d_in[0];
    const float* Wu     = (const float*)d_in[1];
    const float* bu     = (const float*)d_in[2];
    const float* Wv     = (const float*)d_in[3];
    const float* bv     = (const float*)d_in[4];
    const float* Wo     = (const float*)d_in[5];
    const float* bo     = (const float*)d_in[6];
    const float* a_pos  = (const float*)d_in[7];
    const float* b_pos  = (const float*)d_in[8];
    const float* a_neg  = (const float*)d_in[9];
    const float* b_neg  = (const float*)d_in[10];
    const float* t_zero = (const float*)d_in[11];
    float* out = (float*)d_out;

    cudaError_t e3 = cudaFuncSetAttribute(gemm_f16_split3,
                                          cudaFuncAttributeMaxDynamicSharedMemorySize,
                                          GEMM3S_SMEM);
    bool use3 = (e3 == cudaSuccess);
    cudaGetLastError();

    coef_kernel<<<dim3(NHEAD, 2), 128>>>(a_pos, b_pos, a_neg, b_neg);

    convert_split_x<<<RTOT * DMODEL / 4 / 256, 256>>>(x);

    dim3 g12(RTOT / 128, D1 / 128);
    dim3 g3(RTOT / 128, DMODEL / 128);

    transpose_split<<<dim3(D1 / 32, DMODEL / 32), 256>>>(Wu, DMODEL, D1, 0, 0);
    if (use3) gemm_f16_split3<<<g12, 256, GEMM3S_SMEM>>>(bu, nullptr, DMODEL, RTOT, 0, 0, 0);
    else      gemm_f16_split2<<<g12, 256, GEMM2S_SMEM>>>(bu, nullptr, DMODEL, RTOT, 0, 0, 0);

    transpose_split<<<dim3(D1 / 32, DMODEL / 32), 256>>>(Wv, DMODEL, D1, 0, 0);
    if (use3) gemm_f16_split3<<<g12, 256, GEMM3S_SMEM>>>(bv, nullptr, DMODEL, RTOT, 0, 0, 1);
    else      gemm_f16_split2<<<g12, 256, GEMM2S_SMEM>>>(bv, nullptr, DMODEL, RTOT, 0, 0, 1);

    scan_combine_kernel<<<D1 * BATCH, 256>>>(t_zero);

    transpose_split<<<dim3(RTOT / 32, D1 / 32), 256>>>(nullptr, D1, RTOT, 1, 1);
    transpose_split<<<dim3(DMODEL / 32, D1 / 32), 256>>>(Wo, D1, DMODEL, 0, 0);

    if (use3) gemm_f16_split3<<<g3, 256, GEMM3S_SMEM>>>(bo, out, D1, DMODEL, 1, 1, 2);
    else      gemm_f16_split2<<<g3, 256, GEMM2S_SMEM>>>(bo, out, D1, DMODEL, 1, 1, 2);
}

// round 12
// speedup vs baseline: 1.4546x; 1.4546x over previous
#include <cuda_runtime.h>
#include <cuda_fp16.h>
#include <cstdint>
#include <math.h>

// ---------------- problem constants ----------------
#define SEQ     2048
#define BATCH   2
#define RTOT    4096      // BATCH*SEQ
#define DMODEL  1024
#define D1      2048
#define NHEAD   16
#define HDIM    128
#define NKP     16
#define RANKC   32
#define GAMMA_F 0.999f
#define NSEG    15

__device__ __constant__ float G8 =
    (float)(0.999*0.999*0.999*0.999*0.999*0.999*0.999*0.999);
__constant__ int c_OFF[NSEG] = {1,138,274,411,547,683,820,956,1093,1229,1365,1502,1638,1775,1911};

// ---------------- device-global scratch (NEVER passed from host) ----------------
__device__ __align__(128) float g_Ut[(size_t)D1 * RTOT]; // U^T  [c][m]
__device__ __align__(128) float g_Vt[(size_t)D1 * RTOT]; // V^T  [c][m]
__device__ __align__(128) float g_Gt[(size_t)D1 * RTOT]; // gated [c][m]
__device__ __align__(128) float g_CE [NSEG * D1];
__device__ __align__(128) float g_CF [NSEG * D1];
__device__ __align__(128) float g_CEn[NSEG * D1];
__device__ __align__(128) float g_CFn[NSEG * D1];
// split-precision fp16 planes
__device__ __align__(128) __half g_xh [(size_t)RTOT * DMODEL];
__device__ __align__(128) __half g_xl [(size_t)RTOT * DMODEL];
__device__ __align__(128) __half g_Wth[(size_t)D1 * DMODEL];
__device__ __align__(128) __half g_Ath[(size_t)RTOT * D1];
__device__ __align__(128) __half g_Atl[(size_t)RTOT * D1];

// ---------------- helpers ----------------
__device__ __forceinline__ uint32_t smem_to_u32(const void* p) {
    uint32_t a;
    asm("{ .reg .u64 t; cvta.to.shared.u64 t, %1; cvt.u32.u64 %0, t; }" : "=r"(a) : "l"(p));
    return a;
}
#define SMEM_SW64(o) ((o) ^ (((o) >> 3) & 0x30))
__device__ __forceinline__ float silu_f(float x) { return x / (1.0f + expf(-x)); }

#define LDM4(r, addr) \
    asm volatile("ldmatrix.sync.aligned.m8n8.x4.shared.b16 {%0,%1,%2,%3}, [%4];" \
        : "=r"((r)[0]), "=r"((r)[1]), "=r"((r)[2]), "=r"((r)[3]) : "r"(addr))
#define MMA16816(c, a, b0, b1) \
    asm volatile("mma.sync.aligned.m16n8k16.row.col.f32.f16.f16.f32 " \
        "{%0,%1,%2,%3}, {%4,%5,%6,%7}, {%8,%9}, {%0,%1,%2,%3};" \
        : "+f"((c)[0]), "+f"((c)[1]), "+f"((c)[2]), "+f"((c)[3]) \
        : "r"((a)[0]), "r"((a)[1]), "r"((a)[2]), "r"((a)[3]), "r"(b0), "r"(b1))
#define CP16(dst, src) \
    asm volatile("cp.async.cg.shared.global [%0], [%1], 16;" :: "r"(dst), "l"(src) : "memory")
#define CP_COMMIT()  asm volatile("cp.async.commit_group;" ::: "memory")
#define CP_WAIT1()   asm volatile("cp.async.wait_group 1;" ::: "memory")
#define CP_WAIT0()   asm volatile("cp.async.wait_group 0;" ::: "memory")

// ---------------- coefficient kernel ----------------
__global__ void coef_kernel(const float* __restrict__ a_pos, const float* __restrict__ b_pos,
                            const float* __restrict__ a_neg, const float* __restrict__ b_neg)
{
    int h = blockIdx.x;
    int d = threadIdx.x;
    bool neg = (blockIdx.y != 0);
    const float* A  = neg ? a_neg : a_pos;
    const float* Bm = neg ? b_neg : b_pos;
    float* CE = neg ? g_CEn : g_CE;
    float* CF = neg ? g_CFn : g_CF;

    __shared__ float sa[NKP][RANKC];
    for (int i = threadIdx.x; i < NKP * RANKC; i += 128)
        sa[i / RANKC][i % RANKC] = A[h * NKP * RANKC + i];
    __syncthreads();

    float br[RANKC];
#pragma unroll
    for (int r = 0; r < RANKC; r++)
        br[r] = Bm[((size_t)h * RANKC + r) * HDIM + d];

    float kind[NKP];
#pragma unroll
    for (int k = 0; k < NKP; k++) {
        float s = 0.f;
#pragma unroll
        for (int r = 0; r < RANKC; r++) s += sa[k][r] * br[r];
        kind[k] = s;
    }

    const float cm = 15.0f / 2046.0f;
    int c = h * HDIM + d;
    float Pp = 0.f, Qp = 0.f;
#pragma unroll
    for (int j = 0; j < NSEG; j++) {
        float D = kind[j + 1] - kind[j];
        float P = kind[j] - (cm + (float)j) * D;
        float Q = cm * D;
        int O = c_OFF[j];
        float gp = (float)pow((double)0.999, (double)O);
        CE[j * D1 + c] = gp * ((P - Pp) + (Q - Qp) * (float)O);
        CF[j * D1 + c] = gp * (Q - Qp);
        Pp = P; Qp = Q;
    }
}

// ---------------- x -> fp16 hi/lo ----------------
__global__ __launch_bounds__(256)
void convert_split_x(const float* __restrict__ src)
{
    __half* dh = g_xh;
    __half* dl = g_xl;
    int i = blockIdx.x * blockDim.x + threadIdx.x;
    float4 v = ((const float4*)src)[i];
    float vv[4] = {v.x, v.y, v.z, v.w};
    __half h[4], l[4];
#pragma unroll
    for (int j = 0; j < 4; j++) {
        h[j] = __float2half_rn(vv[j]);
        l[j] = __float2half_rn(vv[j] - __half2float(h[j]));
    }
    ((__half2*)dh)[2*i]   = __halves2half2(h[0], h[1]);
    ((__half2*)dh)[2*i+1] = __halves2half2(h[2], h[3]);
    ((__half2*)dl)[2*i]   = __halves2half2(l[0], l[1]);
    ((__half2*)dl)[2*i+1] = __halves2half2(l[2], l[3]);
}

// transpose fp32 [R][C] -> fp16 [C][R]; optionally also lo-plane.
__global__ __launch_bounds__(256)
void transpose_split(const float* __restrict__ src_ext, int R, int C,
                     int src_is_gt, int dst_sel)
{
    const float* src = src_is_gt ? g_Gt : src_ext;
    __half* dh = dst_sel ? g_Ath : g_Wth;
    __half* dl = g_Atl;

    __shared__ float tile[32][33];
    int c0 = blockIdx.x * 32, r0 = blockIdx.y * 32;
    int tx = threadIdx.x & 31, ty = threadIdx.x >> 5;  // (32,8)
#pragma unroll
    for (int j = 0; j < 4; j++)
        tile[ty + 8 * j][tx] = src[(size_t)(r0 + ty + 8 * j) * C + c0 + tx];
    __syncthreads();
#pragma unroll
    for (int j = 0; j < 4; j++) {
        float v = tile[tx][ty + 8 * j];
        size_t o = (size_t)(c0 + ty + 8 * j) * R + r0 + tx;
        __half h = __float2half_rn(v);
        dh[o] = h;
        if (dst_sel) dl[o] = __float2half_rn(v - __half2float(h));
    }
}

// ---------------- split-fp32 GEMM: 2-pass, 128x64 tile (R7 structure) ----------------
// KC=32 per stage, 2 stages in 40KB (no opt-in). Warp tile 64x16 (8 warps, 2x4).
// a_sel: 0 -> (g_xh,g_xl), 1 -> (g_Ath,g_Atl).  B is g_Wth (fp16 trunc).
// mode 0: C[n][m] = silu(acc+bias[n]) into (c_sel ? g_Vt : g_Ut), stride RTOT.
// mode 1: ext_out[m][n] = acc + bias[n].
#define GM_KC    32
#define ST_AH    0
#define ST_AL    8192
#define ST_BH    16384
#define STAGE_SZ 20480
#define GEMM_SMEM (2 * STAGE_SZ)

__global__ __launch_bounds__(256, 3)
void gemm_f16_split(const float* __restrict__ bias, float* __restrict__ ext_out,
                    int Ktot, int strideC, int mode, int a_sel, int c_sel)
{
    const __half* Ah = a_sel ? g_Ath : g_xh;
    const __half* Al = a_sel ? g_Atl : g_xl;
    const __half* Bh = g_Wth;
    float* Cout = (mode == 1) ? ext_out : (c_sel ? g_Vt : g_Ut);

    extern __shared__ char dsm[];
    uint32_t sbase = smem_to_u32(dsm);
    int tid = threadIdx.x;
    int wid = tid >> 5, lane = tid & 31;
    int m0 = blockIdx.x * 128, n0 = blockIdx.y * 64;
    int wm = wid & 1;        // 0..1 : 64-row band
    int wn = wid >> 1;       // 0..3 : 16-col band

    // ldmatrix lane address components
    int a_r = (lane & 7) + ((lane >> 3) & 1) * 8;   // A row within m16
    int a_c = (lane >> 4) * 16;                     // A k-half byte offset
    int b_r = (lane & 7) + ((lane >> 4) & 1) * 8;   // B n-row (two n-tiles)
    int b_c = ((lane >> 3) & 1) * 16;               // B k-half byte offset

    float acc[4][2][4];
#pragma unroll
    for (int i = 0; i < 4; i++)
#pragma unroll
        for (int j = 0; j < 2; j++)
#pragma unroll
            for (int q = 0; q < 4; q++) acc[i][j][q] = 0.f;

    const __half* pAH = Ah + (size_t)m0 * Ktot;
    const __half* pAL = Al + (size_t)m0 * Ktot;
    const __half* pBH = Bh + (size_t)n0 * Ktot;

    // staging indices: A row = tid>>2 (0..63, +64), seg = tid&3 (16B granule)
    int sa_row = tid >> 2, sa_seg = tid & 3;
    uint32_t sa_off  = SMEM_SW64((uint32_t)(sa_row * 64 + sa_seg * 16));
    uint32_t sa_off2 = SMEM_SW64((uint32_t)((sa_row + 64) * 64 + sa_seg * 16));

    int nkc = Ktot / GM_KC;

    auto load_chunk = [&](int kc, int s) {
        int k0 = kc * GM_KC;
        uint32_t st = sbase + s * STAGE_SZ;
        CP16(st + ST_AH + sa_off,  pAH + (size_t)sa_row * Ktot + k0 + sa_seg * 8);
        CP16(st + ST_AH + sa_off2, pAH + (size_t)(sa_row + 64) * Ktot + k0 + sa_seg * 8);
        CP16(st + ST_AL + sa_off,  pAL + (size_t)sa_row * Ktot + k0 + sa_seg * 8);
        CP16(st + ST_AL + sa_off2, pAL + (size_t)(sa_row + 64) * Ktot + k0 + sa_seg * 8);
        if (sa_row < 64)
            CP16(st + ST_BH + sa_off, pBH + (size_t)sa_row * Ktot + k0 + sa_seg * 8);
    };

    load_chunk(0, 0);
    CP_COMMIT();

    for (int kc = 0; kc < nkc; kc++) {
        int s = kc & 1;
        if (kc + 1 < nkc) {
            load_chunk(kc + 1, s ^ 1);
            CP_COMMIT();
            CP_WAIT1();
        } else {
            CP_WAIT0();
        }
        __syncthreads();

        uint32_t st = sbase + s * STAGE_SZ;
#pragma unroll
        for (int ks = 0; ks < 2; ks++) {
            // batched fragment loads (proven R7 pattern)
            uint32_t aH[4][4], aL[4][4];
#pragma unroll
            for (int mt = 0; mt < 4; mt++) {
                int m = wm * 64 + mt * 16 + a_r;
                uint32_t off = SMEM_SW64((uint32_t)(m * 64 + ks * 32 + a_c));
                LDM4(aH[mt], st + ST_AH + off);
                LDM4(aL[mt], st + ST_AL + off);
            }
            uint32_t bH[4];   // r0,r1 = n-tile0; r2,r3 = n-tile1
            {
                int n = wn * 16 + b_r;
                uint32_t off = SMEM_SW64((uint32_t)(n * 64 + ks * 32 + b_c));
                LDM4(bH, st + ST_BH + off);
            }
#pragma unroll
            for (int mt = 0; mt < 4; mt++) {
                MMA16816(acc[mt][0], aH[mt], bH[0], bH[1]);
                MMA16816(acc[mt][0], aL[mt], bH[0], bH[1]);
                MMA16816(acc[mt][1], aH[mt], bH[2], bH[3]);
                MMA16816(acc[mt][1], aL[mt], bH[2], bH[3]);
            }
        }
        __syncthreads();
    }

    // epilogue: c0=(m,n), c1=(m,n+1), c2=(m+8,n), c3=(m+8,n+1)
    int er = lane >> 2, ec = (lane & 3) * 2;
#pragma unroll
    for (int mt = 0; mt < 4; mt++) {
#pragma unroll
        for (int nt = 0; nt < 2; nt++) {
            int mA = m0 + wm * 64 + mt * 16 + er;
            int nA = n0 + wn * 16 + nt * 8 + ec;
            float b0 = bias[nA], b1 = bias[nA + 1];
            float* c = acc[mt][nt];
            if (mode == 0) {
                Cout[(size_t)nA * strideC + mA]           = silu_f(c[0] + b0);
                Cout[(size_t)(nA + 1) * strideC + mA]     = silu_f(c[1] + b1);
                Cout[(size_t)nA * strideC + mA + 8]       = silu_f(c[2] + b0);
                Cout[(size_t)(nA + 1) * strideC + mA + 8] = silu_f(c[3] + b1);
            } else {
                Cout[(size_t)mA * strideC + nA]           = c[0] + b0;
                Cout[(size_t)mA * strideC + nA + 1]       = c[1] + b1;
                Cout[(size_t)(mA + 8) * strideC + nA]     = c[2] + b0;
                Cout[(size_t)(mA + 8) * strideC + nA + 1] = c[3] + b1;
            }
        }
    }
}

// ---------------- fused scan + combine (proven R9/R10 version) ----------------
__device__ void scan_pass(const float* sv, float* sa, float* sk, float* sp, float* sq,
                          float* oe, float* of, int tid, bool rev)
{
    float vloc[8];
    int base = tid * 8;
#pragma unroll
    for (int i = 0; i < 8; i++)
        vloc[i] = sv[rev ? (SEQ - 1 - (base + i)) : (base + i)];

    float e = 0.f, f = 0.f;
#pragma unroll
    for (int i = 0; i < 8; i++) { f = GAMMA_F * (f + e); e = GAMMA_F * e + vloc[i]; }
    sa[tid] = G8; sk[tid] = 8.f; sp[tid] = e; sq[tid] = f;
    __syncthreads();

    for (int d = 1; d < 256; d <<= 1) {
        float pa = 0.f, pk = 0.f, pp = 0.f, pq = 0.f;
        bool has = tid >= d;
        if (has) { pa = sa[tid - d]; pk = sk[tid - d]; pp = sp[tid - d]; pq = sq[tid - d]; }
        float ca = sa[tid], ck = sk[tid], cp = sp[tid], cq = sq[tid];
        __syncthreads();
        if (has) {
            sp[tid] = ca * pp + cp;
            sq[tid] = ca * pq + ca * ck * pp + cq;
            sa[tid] = pa * ca;
            sk[tid] = pk + ck;
        }
        __syncthreads();
    }
    float E0 = tid ? sp[tid - 1] : 0.f;
    float F0 = tid ? sq[tid - 1] : 0.f;
    e = E0; f = F0;
#pragma unroll
    for (int i = 0; i < 8; i++) {
        float fn = GAMMA_F * (f + e);
        e = GAMMA_F * e + vloc[i];
        f = fn;
        int t = base + i;
        int o = rev ? (SEQ - 1 - t) : t;
        oe[o] = e; of[o] = f;
    }
    __syncthreads();
}

__global__ __launch_bounds__(256)
void scan_combine_kernel(const float* __restrict__ t_zero)
{
    int c = blockIdx.x >> 1;
    int b = blockIdx.x & 1;
    size_t base = (size_t)c * RTOT + (size_t)b * SEQ;

    __shared__ float sv[SEQ], se[SEQ], sf[SEQ], sg[SEQ], sh2[SEQ];
    __shared__ float sa[256], sk[256], sp[256], sq[256];
    __shared__ float sCE[NSEG], sCF[NSEG], sCEn[NSEG], sCFn[NSEG];
    int tid = threadIdx.x;
    const float4* vin = (const float4*)(g_Vt + base);
    for (int i = tid; i < SEQ / 4; i += 256) ((float4*)sv)[i] = vin[i];
    if (tid < NSEG) {
        sCE [tid] = g_CE [tid * D1 + c];
        sCF [tid] = g_CF [tid * D1 + c];
        sCEn[tid] = g_CEn[tid * D1 + c];
        sCFn[tid] = g_CFn[tid * D1 + c];
    }
    float tz = t_zero[c];
    __syncthreads();

    scan_pass(sv, sa, sk, sp, sq, se,  sf,  tid, false);
    scan_pass(sv, sa, sk, sp, sq, sg, sh2, tid, true);

#pragma unroll
    for (int rpt = 0; rpt < 8; rpt++) {
        int t = tid + rpt * 256;
        float acc = tz * sv[t];
#pragma unroll
        for (int m = 0; m < NSEG; m++) {
            int o = c_OFF[m];
            int tm = t - o;
            if (tm >= 0)  acc += sCE[m]  * se[tm] + sCF[m]  * sf[tm];
            int tp = t + o;
            if (tp < SEQ) acc += sCEn[m] * sg[tp] + sCFn[m] * sh2[tp];
        }
        float uu = g_Ut[base + t];
        g_Gt[base + t] = acc * uu;
    }
}

// ---------------- launch ----------------
extern "C" void kernel_launch(void* const* d_in, const int* in_sizes, int n_in,
                              void* d_out, int out_size)
{
    (void)in_sizes; (void)n_in; (void)out_size;
    const float* x      = (const float*)d_in[0];
    const float* Wu     = (const float*)d_in[1];
    const float* bu     = (const float*)d_in[2];
    const float* Wv     = (const float*)d_in[3];
    const float* bv     = (const float*)d_in[4];
    const float* Wo     = (const float*)d_in[5];
    const float* bo     = (const float*)d_in[6];
    const float* a_pos  = (const float*)d_in[7];
    const float* b_pos  = (const float*)d_in[8];
    const float* a_neg  = (const float*)d_in[9];
    const float* b_neg  = (const float*)d_in[10];
    const float* t_zero = (const float*)d_in[11];
    float* out = (float*)d_out;

    coef_kernel<<<dim3(NHEAD, 2), 128>>>(a_pos, b_pos, a_neg, b_neg);

    // x -> fp16 hi/lo planes
    convert_split_x<<<RTOT * DMODEL / 4 / 256, 256>>>(x);

    dim3 g12(RTOT / 128, D1 / 64);
    dim3 g3(RTOT / 128, DMODEL / 64);

    // GEMM1: U^T = silu(x @ Wu + bu)^T
    transpose_split<<<dim3(D1 / 32, DMODEL / 32), 256>>>(Wu, DMODEL, D1, 0, 0);
    gemm_f16_split<<<g12, 256, GEMM_SMEM>>>(bu, nullptr, DMODEL, RTOT, 0, 0, 0);

    // GEMM2: V^T = silu(x @ Wv + bv)^T
    transpose_split<<<dim3(D1 / 32, DMODEL / 32), 256>>>(Wv, DMODEL, D1, 0, 0);
    gemm_f16_split<<<g12, 256, GEMM_SMEM>>>(bv, nullptr, DMODEL, RTOT, 0, 0, 1);

    // fused scans + combine -> g_Gt [c][m]
    scan_combine_kernel<<<D1 * BATCH, 256>>>(t_zero);

    // Gt [k][m] -> A3 [m][k] hi/lo ; Wo [k][n] -> B3 [n][k] hi
    transpose_split<<<dim3(RTOT / 32, D1 / 32), 256>>>(nullptr, D1, RTOT, 1, 1);
    transpose_split<<<dim3(DMODEL / 32, D1 / 32), 256>>>(Wo, D1, DMODEL, 0, 0);

    // GEMM3: out = Gt^T @ Wo + bo
    gemm_f16_split<<<g3, 256, GEMM_SMEM>>>(bo, out, D1, DMODEL, 1, 1, 2);
}

// round 14
// speedup vs baseline: 1.4883x; 1.0232x over previous
#include <cuda_runtime.h>
#include <cuda_fp16.h>
#include <cstdint>
#include <math.h>

// ---------------- problem constants ----------------
#define SEQ     2048
#define BATCH   2
#define RTOT    4096      // BATCH*SEQ
#define DMODEL  1024
#define D1      2048
#define NHEAD   16
#define HDIM    128
#define NKP     16
#define RANKC   32
#define GAMMA_F 0.999f
#define NSEG    15

__device__ __constant__ float G8 =
    (float)(0.999*0.999*0.999*0.999*0.999*0.999*0.999*0.999);
__constant__ int c_OFF[NSEG] = {1,138,274,411,547,683,820,956,1093,1229,1365,1502,1638,1775,1911};

// ---------------- device-global scratch (NEVER passed from host) ----------------
__device__ __align__(128) float g_Ut[(size_t)D1 * RTOT]; // U^T  [c][m]
__device__ __align__(128) float g_Vt[(size_t)D1 * RTOT]; // V^T  [c][m]
__device__ __align__(128) float g_CE [NSEG * D1];
__device__ __align__(128) float g_CF [NSEG * D1];
__device__ __align__(128) float g_CEn[NSEG * D1];
__device__ __align__(128) float g_CFn[NSEG * D1];
// split-precision fp16 planes
__device__ __align__(128) __half g_xh [(size_t)RTOT * DMODEL];
__device__ __align__(128) __half g_xl [(size_t)RTOT * DMODEL];
__device__ __align__(128) __half g_Wth[(size_t)D1 * DMODEL];
__device__ __align__(128) __half g_Ath[(size_t)D1 * RTOT];  // gated hi, [k][m]
__device__ __align__(128) __half g_Atl[(size_t)D1 * RTOT];  // gated lo, [k][m]

// ---------------- helpers ----------------
__device__ __forceinline__ uint32_t smem_to_u32(const void* p) {
    uint32_t a;
    asm("{ .reg .u64 t; cvta.to.shared.u64 t, %1; cvt.u32.u64 %0, t; }" : "=r"(a) : "l"(p));
    return a;
}
#define SMEM_SW64(o) ((o) ^ (((o) >> 3) & 0x30))
__device__ __forceinline__ float silu_f(float x) { return x / (1.0f + expf(-x)); }

#define LDM4(r, addr) \
    asm volatile("ldmatrix.sync.aligned.m8n8.x4.shared.b16 {%0,%1,%2,%3}, [%4];" \
        : "=r"((r)[0]), "=r"((r)[1]), "=r"((r)[2]), "=r"((r)[3]) : "r"(addr))
#define LDM4T(r, addr) \
    asm volatile("ldmatrix.sync.aligned.m8n8.x4.trans.shared.b16 {%0,%1,%2,%3}, [%4];" \
        : "=r"((r)[0]), "=r"((r)[1]), "=r"((r)[2]), "=r"((r)[3]) : "r"(addr))
#define MMA16816(c, a, b0, b1) \
    asm volatile("mma.sync.aligned.m16n8k16.row.col.f32.f16.f16.f32 " \
        "{%0,%1,%2,%3}, {%4,%5,%6,%7}, {%8,%9}, {%0,%1,%2,%3};" \
        : "+f"((c)[0]), "+f"((c)[1]), "+f"((c)[2]), "+f"((c)[3]) \
        : "r"((a)[0]), "r"((a)[1]), "r"((a)[2]), "r"((a)[3]), "r"(b0), "r"(b1))
#define CP16(dst, src) \
    asm volatile("cp.async.cg.shared.global [%0], [%1], 16;" :: "r"(dst), "l"(src) : "memory")
#define CP_COMMIT()  asm volatile("cp.async.commit_group;" ::: "memory")
#define CP_WAIT1()   asm volatile("cp.async.wait_group 1;" ::: "memory")
#define CP_WAIT0()   asm volatile("cp.async.wait_group 0;" ::: "memory")

// ---------------- coefficient kernel ----------------
__global__ void coef_kernel(const float* __restrict__ a_pos, const float* __restrict__ b_pos,
                            const float* __restrict__ a_neg, const float* __restrict__ b_neg)
{
    int h = blockIdx.x;
    int d = threadIdx.x;
    bool neg = (blockIdx.y != 0);
    const float* A  = neg ? a_neg : a_pos;
    const float* Bm = neg ? b_neg : b_pos;
    float* CE = neg ? g_CEn : g_CE;
    float* CF = neg ? g_CFn : g_CF;

    __shared__ float sa[NKP][RANKC];
    for (int i = threadIdx.x; i < NKP * RANKC; i += 128)
        sa[i / RANKC][i % RANKC] = A[h * NKP * RANKC + i];
    __syncthreads();

    float br[RANKC];
#pragma unroll
    for (int r = 0; r < RANKC; r++)
        br[r] = Bm[((size_t)h * RANKC + r) * HDIM + d];

    float kind[NKP];
#pragma unroll
    for (int k = 0; k < NKP; k++) {
        float s = 0.f;
#pragma unroll
        for (int r = 0; r < RANKC; r++) s += sa[k][r] * br[r];
        kind[k] = s;
    }

    const float cm = 15.0f / 2046.0f;
    int c = h * HDIM + d;
    float Pp = 0.f, Qp = 0.f;
#pragma unroll
    for (int j = 0; j < NSEG; j++) {
        float D = kind[j + 1] - kind[j];
        float P = kind[j] - (cm + (float)j) * D;
        float Q = cm * D;
        int O = c_OFF[j];
        float gp = (float)pow((double)0.999, (double)O);
        CE[j * D1 + c] = gp * ((P - Pp) + (Q - Qp) * (float)O);
        CF[j * D1 + c] = gp * (Q - Qp);
        Pp = P; Qp = Q;
    }
}

// ---------------- x -> fp16 hi/lo ----------------
__global__ __launch_bounds__(256)
void convert_split_x(const float* __restrict__ src)
{
    __half* dh = g_xh;
    __half* dl = g_xl;
    int i = blockIdx.x * blockDim.x + threadIdx.x;
    float4 v = ((const float4*)src)[i];
    float vv[4] = {v.x, v.y, v.z, v.w};
    __half h[4], l[4];
#pragma unroll
    for (int j = 0; j < 4; j++) {
        h[j] = __float2half_rn(vv[j]);
        l[j] = __float2half_rn(vv[j] - __half2float(h[j]));
    }
    ((__half2*)dh)[2*i]   = __halves2half2(h[0], h[1]);
    ((__half2*)dh)[2*i+1] = __halves2half2(h[2], h[3]);
    ((__half2*)dl)[2*i]   = __halves2half2(l[0], l[1]);
    ((__half2*)dl)[2*i+1] = __halves2half2(l[2], l[3]);
}

// transpose fp32 weight [R][C] -> fp16 hi [C][R] (into g_Wth)
__global__ __launch_bounds__(256)
void transpose_w(const float* __restrict__ src, int R, int C)
{
    __half* dh = g_Wth;
    __shared__ float tile[32][33];
    int c0 = blockIdx.x * 32, r0 = blockIdx.y * 32;
    int tx = threadIdx.x & 31, ty = threadIdx.x >> 5;  // (32,8)
#pragma unroll
    for (int j = 0; j < 4; j++)
        tile[ty + 8 * j][tx] = src[(size_t)(r0 + ty + 8 * j) * C + c0 + tx];
    __syncthreads();
#pragma unroll
    for (int j = 0; j < 4; j++) {
        float v = tile[tx][ty + 8 * j];
        dh[(size_t)(c0 + ty + 8 * j) * R + r0 + tx] = __float2half_rn(v);
    }
}

// ---------------- GEMM 1/2: 2-pass, 128x64 tile, A m-major (R12 proven) ----------------
#define GM_KC    32
#define ST_AH    0
#define ST_AL    8192
#define ST_BH    16384
#define STAGE_SZ 20480
#define GEMM_SMEM (2 * STAGE_SZ)

__global__ __launch_bounds__(256, 3)
void gemm_f16_split(const float* __restrict__ bias, int Ktot, int c_sel)
{
    const __half* Ah = g_xh;
    const __half* Al = g_xl;
    const __half* Bh = g_Wth;
    float* Cout = c_sel ? g_Vt : g_Ut;
    const int strideC = RTOT;

    extern __shared__ char dsm[];
    uint32_t sbase = smem_to_u32(dsm);
    int tid = threadIdx.x;
    int wid = tid >> 5, lane = tid & 31;
    int m0 = blockIdx.x * 128, n0 = blockIdx.y * 64;
    int wm = wid & 1;
    int wn = wid >> 1;

    int a_r = (lane & 7) + ((lane >> 3) & 1) * 8;
    int a_c = (lane >> 4) * 16;
    int b_r = (lane & 7) + ((lane >> 4) & 1) * 8;
    int b_c = ((lane >> 3) & 1) * 16;

    float acc[4][2][4];
#pragma unroll
    for (int i = 0; i < 4; i++)
#pragma unroll
        for (int j = 0; j < 2; j++)
#pragma unroll
            for (int q = 0; q < 4; q++) acc[i][j][q] = 0.f;

    const __half* pAH = Ah + (size_t)m0 * Ktot;
    const __half* pAL = Al + (size_t)m0 * Ktot;
    const __half* pBH = Bh + (size_t)n0 * Ktot;

    int sa_row = tid >> 2, sa_seg = tid & 3;
    uint32_t sa_off  = SMEM_SW64((uint32_t)(sa_row * 64 + sa_seg * 16));
    uint32_t sa_off2 = SMEM_SW64((uint32_t)((sa_row + 64) * 64 + sa_seg * 16));

    int nkc = Ktot / GM_KC;

    auto load_chunk = [&](int kc, int s) {
        int k0 = kc * GM_KC;
        uint32_t st = sbase + s * STAGE_SZ;
        CP16(st + ST_AH + sa_off,  pAH + (size_t)sa_row * Ktot + k0 + sa_seg * 8);
        CP16(st + ST_AH + sa_off2, pAH + (size_t)(sa_row + 64) * Ktot + k0 + sa_seg * 8);
        CP16(st + ST_AL + sa_off,  pAL + (size_t)sa_row * Ktot + k0 + sa_seg * 8);
        CP16(st + ST_AL + sa_off2, pAL + (size_t)(sa_row + 64) * Ktot + k0 + sa_seg * 8);
        CP16(st + ST_BH + sa_off,  pBH + (size_t)sa_row * Ktot + k0 + sa_seg * 8);
    };

    load_chunk(0, 0);
    CP_COMMIT();

    for (int kc = 0; kc < nkc; kc++) {
        int s = kc & 1;
        if (kc + 1 < nkc) {
            load_chunk(kc + 1, s ^ 1);
            CP_COMMIT();
            CP_WAIT1();
        } else {
            CP_WAIT0();
        }
        __syncthreads();

        uint32_t st = sbase + s * STAGE_SZ;
#pragma unroll
        for (int ks = 0; ks < 2; ks++) {
            uint32_t aH[4][4], aL[4][4];
#pragma unroll
            for (int mt = 0; mt < 4; mt++) {
                int m = wm * 64 + mt * 16 + a_r;
                uint32_t off = SMEM_SW64((uint32_t)(m * 64 + ks * 32 + a_c));
                LDM4(aH[mt], st + ST_AH + off);
                LDM4(aL[mt], st + ST_AL + off);
            }
            uint32_t bH[4];
            {
                int n = wn * 16 + b_r;
                uint32_t off = SMEM_SW64((uint32_t)(n * 64 + ks * 32 + b_c));
                LDM4(bH, st + ST_BH + off);
            }
#pragma unroll
            for (int mt = 0; mt < 4; mt++) {
                MMA16816(acc[mt][0], aH[mt], bH[0], bH[1]);
                MMA16816(acc[mt][0], aL[mt], bH[0], bH[1]);
                MMA16816(acc[mt][1], aH[mt], bH[2], bH[3]);
                MMA16816(acc[mt][1], aL[mt], bH[2], bH[3]);
            }
        }
        __syncthreads();
    }

    int er = lane >> 2, ec = (lane & 3) * 2;
#pragma unroll
    for (int mt = 0; mt < 4; mt++) {
#pragma unroll
        for (int nt = 0; nt < 2; nt++) {
            int mA = m0 + wm * 64 + mt * 16 + er;
            int nA = n0 + wn * 16 + nt * 8 + ec;
            float b0 = bias[nA], b1 = bias[nA + 1];
            float* c = acc[mt][nt];
            Cout[(size_t)nA * strideC + mA]           = silu_f(c[0] + b0);
            Cout[(size_t)(nA + 1) * strideC + mA]     = silu_f(c[1] + b1);
            Cout[(size_t)nA * strideC + mA + 8]       = silu_f(c[2] + b0);
            Cout[(size_t)(nA + 1) * strideC + mA + 8] = silu_f(c[3] + b1);
        }
    }
}

// ---------------- GEMM 3: A k-major via ldmatrix.trans ----------------
// A = g_Ath/g_Atl [k][m] (m contiguous). B = g_Wth [n][k]. out[m][n] += bias[n].
// A stage: 32 k-rows x 256B m; swizzle granule 16B: (moff*2) ^ ((k&7)*16).
__global__ __launch_bounds__(256, 3)
void gemm_f16_at(const float* __restrict__ bias, float* __restrict__ ext_out, int Ktot)
{
    const __half* Bh = g_Wth;
    extern __shared__ char dsm[];
    uint32_t sbase = smem_to_u32(dsm);
    int tid = threadIdx.x;
    int wid = tid >> 5, lane = tid & 31;
    int m0 = blockIdx.x * 128, n0 = blockIdx.y * 64;
    int wm = wid & 1;
    int wn = wid >> 1;

    int b_r = (lane & 7) + ((lane >> 4) & 1) * 8;
    int b_c = ((lane >> 3) & 1) * 16;
    // trans-A lane addressing (within 32-row chunk)
    int at_k8 = ((lane >> 4) & 1) * 8 + (lane & 7);    // k row within 16-k group
    int at_m8 = ((lane >> 3) & 1) * 8;                 // m sub-offset

    float acc[4][2][4];
#pragma unroll
    for (int i = 0; i < 4; i++)
#pragma unroll
        for (int j = 0; j < 2; j++)
#pragma unroll
            for (int q = 0; q < 4; q++) acc[i][j][q] = 0.f;

    const __half* pBH = Bh + (size_t)n0 * Ktot;

    // B staging indices (same as gemm_f16_split)
    int sb_row = tid >> 2, sb_seg = tid & 3;
    uint32_t sb_off = SMEM_SW64((uint32_t)(sb_row * 64 + sb_seg * 16));
    // A staging indices: row = tid>>3 (0..31), granule = tid&7 (and +8)
    int ar = tid >> 3, ag = tid & 7;
    uint32_t a_sw1 = (uint32_t)(ar * 256 + ((ag * 16) ^ ((ar & 7) * 16)));
    uint32_t a_sw2 = (uint32_t)(ar * 256 + (((ag + 8) * 16) ^ ((ar & 7) * 16)));

    int nkc = Ktot / GM_KC;

    auto load_chunk = [&](int kc, int s) {
        int k0 = kc * GM_KC;
        uint32_t st = sbase + s * STAGE_SZ;
        const __half* srcH = g_Ath + (size_t)(k0 + ar) * RTOT + m0;
        const __half* srcL = g_Atl + (size_t)(k0 + ar) * RTOT + m0;
        CP16(st + ST_AH + a_sw1, srcH + ag * 8);
        CP16(st + ST_AH + a_sw2, srcH + (ag + 8) * 8);
        CP16(st + ST_AL + a_sw1, srcL + ag * 8);
        CP16(st + ST_AL + a_sw2, srcL + (ag + 8) * 8);
        CP16(st + ST_BH + sb_off, pBH + (size_t)sb_row * Ktot + k0 + sb_seg * 8);
    };

    load_chunk(0, 0);
    CP_COMMIT();

    for (int kc = 0; kc < nkc; kc++) {
        int s = kc & 1;
        if (kc + 1 < nkc) {
            load_chunk(kc + 1, s ^ 1);
            CP_COMMIT();
            CP_WAIT1();
        } else {
            CP_WAIT0();
        }
        __syncthreads();

        uint32_t st = sbase + s * STAGE_SZ;
#pragma unroll
        for (int ks = 0; ks < 2; ks++) {
            int k_row = ks * 16 + at_k8;   // 0..31 within chunk
            uint32_t krow_base = (uint32_t)(k_row * 256);
            uint32_t kxor = (uint32_t)((k_row & 7) * 16);
            uint32_t aH[4][4], aL[4][4];
#pragma unroll
            for (int mt = 0; mt < 4; mt++) {
                int moff = wm * 64 + mt * 16 + at_m8;
                uint32_t off = krow_base + (((uint32_t)(moff * 2)) ^ kxor);
                LDM4T(aH[mt], st + ST_AH + off);
                LDM4T(aL[mt], st + ST_AL + off);
            }
            uint32_t bH[4];
            {
                int n = wn * 16 + b_r;
                uint32_t off = SMEM_SW64((uint32_t)(n * 64 + ks * 32 + b_c));
                LDM4(bH, st + ST_BH + off);
            }
#pragma unroll
            for (int mt = 0; mt < 4; mt++) {
                MMA16816(acc[mt][0], aH[mt], bH[0], bH[1]);
                MMA16816(acc[mt][0], aL[mt], bH[0], bH[1]);
                MMA16816(acc[mt][1], aH[mt], bH[2], bH[3]);
                MMA16816(acc[mt][1], aL[mt], bH[2], bH[3]);
            }
        }
        __syncthreads();
    }

    int er = lane >> 2, ec = (lane & 3) * 2;
#pragma unroll
    for (int mt = 0; mt < 4; mt++) {
#pragma unroll
        for (int nt = 0; nt < 2; nt++) {
            int mA = m0 + wm * 64 + mt * 16 + er;
            int nA = n0 + wn * 16 + nt * 8 + ec;
            float b0 = bias[nA], b1 = bias[nA + 1];
            float* c = acc[mt][nt];
            ext_out[(size_t)mA * DMODEL + nA]           = c[0] + b0;
            ext_out[(size_t)mA * DMODEL + nA + 1]       = c[1] + b1;
            ext_out[(size_t)(mA + 8) * DMODEL + nA]     = c[2] + b0;
            ext_out[(size_t)(mA + 8) * DMODEL + nA + 1] = c[3] + b1;
        }
    }
}

// ---------------- fused scan + combine (outputs fp16 hi/lo [k][m]) ----------------
__device__ void scan_pass(const float* sv, float* sa, float* sk, float* sp, float* sq,
                          float* oe, float* of, int tid, bool rev)
{
    float vloc[8];
    int base = tid * 8;
#pragma unroll
    for (int i = 0; i < 8; i++)
        vloc[i] = sv[rev ? (SEQ - 1 - (base + i)) : (base + i)];

    float e = 0.f, f = 0.f;
#pragma unroll
    for (int i = 0; i < 8; i++) { f = GAMMA_F * (f + e); e = GAMMA_F * e + vloc[i]; }
    sa[tid] = G8; sk[tid] = 8.f; sp[tid] = e; sq[tid] = f;
    __syncthreads();

    for (int d = 1; d < 256; d <<= 1) {
        float pa = 0.f, pk = 0.f, pp = 0.f, pq = 0.f;
        bool has = tid >= d;
        if (has) { pa = sa[tid - d]; pk = sk[tid - d]; pp = sp[tid - d]; pq = sq[tid - d]; }
        float ca = sa[tid], ck = sk[tid], cp = sp[tid], cq = sq[tid];
        __syncthreads();
        if (has) {
            sp[tid] = ca * pp + cp;
            sq[tid] = ca * pq + ca * ck * pp + cq;
            sa[tid] = pa * ca;
            sk[tid] = pk + ck;
        }
        __syncthreads();
    }
    float E0 = tid ? sp[tid - 1] : 0.f;
    float F0 = tid ? sq[tid - 1] : 0.f;
    e = E0; f = F0;
#pragma unroll
    for (int i = 0; i < 8; i++) {
        float fn = GAMMA_F * (f + e);
        e = GAMMA_F * e + vloc[i];
        f = fn;
        int t = base + i;
        int o = rev ? (SEQ - 1 - t) : t;
        oe[o] = e; of[o] = f;
    }
    __syncthreads();
}

__global__ __launch_bounds__(256)
void scan_combine_kernel(const float* __restrict__ t_zero)
{
    int c = blockIdx.x >> 1;
    int b = blockIdx.x & 1;
    size_t base = (size_t)c * RTOT + (size_t)b * SEQ;

    __shared__ float sv[SEQ], se[SEQ], sf[SEQ], sg[SEQ], sh2[SEQ];
    __shared__ float sa[256], sk[256], sp[256], sq[256];
    __shared__ float sCE[NSEG], sCF[NSEG], sCEn[NSEG], sCFn[NSEG];
    int tid = threadIdx.x;
    const float4* vin = (const float4*)(g_Vt + base);
    for (int i = tid; i < SEQ / 4; i += 256) ((float4*)sv)[i] = vin[i];
    if (tid < NSEG) {
        sCE [tid] = g_CE [tid * D1 + c];
        sCF [tid] = g_CF [tid * D1 + c];
        sCEn[tid] = g_CEn[tid * D1 + c];
        sCFn[tid] = g_CFn[tid * D1 + c];
    }
    float tz = t_zero[c];
    __syncthreads();

    scan_pass(sv, sa, sk, sp, sq, se,  sf,  tid, false);
    scan_pass(sv, sa, sk, sp, sq, sg, sh2, tid, true);

#pragma unroll
    for (int rpt = 0; rpt < 8; rpt++) {
        int t = tid + rpt * 256;
        float acc = tz * sv[t];
#pragma unroll
        for (int m = 0; m < NSEG; m++) {
            int o = c_OFF[m];
            int tm = t - o;
            if (tm >= 0)  acc += sCE[m]  * se[tm] + sCF[m]  * sf[tm];
            int tp = t + o;
            if (tp < SEQ) acc += sCEn[m] * sg[tp] + sCFn[m] * sh2[tp];
        }
        float val = acc * g_Ut[base + t];
        __half h = __float2half_rn(val);
        g_Ath[base + t] = h;
        g_Atl[base + t] = __float2half_rn(val - __half2float(h));
    }
}

// ---------------- launch ----------------
extern "C" void kernel_launch(void* const* d_in, const int* in_sizes, int n_in,
                              void* d_out, int out_size)
{
    (void)in_sizes; (void)n_in; (void)out_size;
    const float* x      = (const float*)d_in[0];
    const float* Wu     = (const float*)d_in[1];
    const float* bu     = (const float*)d_in[2];
    const float* Wv     = (const float*)d_in[3];
    const float* bv     = (const float*)d_in[4];
    const float* Wo     = (const float*)d_in[5];
    const float* bo     = (const float*)d_in[6];
    const float* a_pos  = (const float*)d_in[7];
    const float* b_pos  = (const float*)d_in[8];
    const float* a_neg  = (const float*)d_in[9];
    const float* b_neg  = (const float*)d_in[10];
    const float* t_zero = (const float*)d_in[11];
    float* out = (float*)d_out;

    coef_kernel<<<dim3(NHEAD, 2), 128>>>(a_pos, b_pos, a_neg, b_neg);

    // x -> fp16 hi/lo planes
    convert_split_x<<<RTOT * DMODEL / 4 / 256, 256>>>(x);

    dim3 g12(RTOT / 128, D1 / 64);
    dim3 g3(RTOT / 128, DMODEL / 64);

    // GEMM1: U^T = silu(x @ Wu + bu)^T
    transpose_w<<<dim3(D1 / 32, DMODEL / 32), 256>>>(Wu, DMODEL, D1);
    gemm_f16_split<<<g12, 256, GEMM_SMEM>>>(bu, DMODEL, 0);

    // GEMM2: V^T = silu(x @ Wv + bv)^T
    transpose_w<<<dim3(D1 / 32, DMODEL / 32), 256>>>(Wv, DMODEL, D1);
    gemm_f16_split<<<g12, 256, GEMM_SMEM>>>(bv, DMODEL, 1);

    // fused scans + combine -> fp16 hi/lo planes [k][m]
    scan_combine_kernel<<<D1 * BATCH, 256>>>(t_zero);

    // Wo [k][n] -> [n][k] fp16
    transpose_w<<<dim3(DMODEL / 32, D1 / 32), 256>>>(Wo, D1, DMODEL);

    // GEMM3: out = Gt^T @ Wo + bo  (A via ldmatrix.trans)
    gemm_f16_at<<<g3, 256, GEMM_SMEM>>>(bo, out, D1);
}

// round 15
// speedup vs baseline: 1.6341x; 1.0980x over previous
#include <cuda_runtime.h>
#include <cuda_fp16.h>
#include <cstdint>
#include <math.h>

// ---------------- problem constants ----------------
#define SEQ     2048
#define BATCH   2
#define RTOT    4096      // BATCH*SEQ
#define DMODEL  1024
#define D1      2048
#define NHEAD   16
#define HDIM    128
#define NKP     16
#define RANKC   32
#define GAMMA_F 0.999f
#define NSEG    15

__device__ __constant__ float G8 =
    (float)(0.999*0.999*0.999*0.999*0.999*0.999*0.999*0.999);
__constant__ int c_OFF[NSEG] = {1,138,274,411,547,683,820,956,1093,1229,1365,1502,1638,1775,1911};

// ---------------- device-global scratch (NEVER passed from host) ----------------
__device__ __align__(128) float g_Ut[(size_t)D1 * RTOT]; // U^T  [c][m]
__device__ __align__(128) float g_Vt[(size_t)D1 * RTOT]; // V^T  [c][m]
__device__ __align__(128) float g_CE [NSEG * D1];
__device__ __align__(128) float g_CF [NSEG * D1];
__device__ __align__(128) float g_CEn[NSEG * D1];
__device__ __align__(128) float g_CFn[NSEG * D1];
// split-precision fp16 planes
__device__ __align__(128) __half g_xh [(size_t)RTOT * DMODEL];
__device__ __align__(128) __half g_xl [(size_t)RTOT * DMODEL];
__device__ __align__(128) __half g_Wth[(size_t)D1 * DMODEL];
__device__ __align__(128) __half g_Ath[(size_t)D1 * RTOT];  // gated hi, [k][m]
__device__ __align__(128) __half g_Atl[(size_t)D1 * RTOT];  // gated lo, [k][m]

// ---------------- helpers ----------------
__device__ __forceinline__ uint32_t smem_to_u32(const void* p) {
    uint32_t a;
    asm("{ .reg .u64 t; cvta.to.shared.u64 t, %1; cvt.u32.u64 %0, t; }" : "=r"(a) : "l"(p));
    return a;
}
#define SMEM_SW64(o) ((o) ^ (((o) >> 3) & 0x30))
__device__ __forceinline__ float silu_f(float x) { return x / (1.0f + expf(-x)); }

#define LDM4(r, addr) \
    asm volatile("ldmatrix.sync.aligned.m8n8.x4.shared.b16 {%0,%1,%2,%3}, [%4];" \
        : "=r"((r)[0]), "=r"((r)[1]), "=r"((r)[2]), "=r"((r)[3]) : "r"(addr))
#define LDM4T(r, addr) \
    asm volatile("ldmatrix.sync.aligned.m8n8.x4.trans.shared.b16 {%0,%1,%2,%3}, [%4];" \
        : "=r"((r)[0]), "=r"((r)[1]), "=r"((r)[2]), "=r"((r)[3]) : "r"(addr))
#define MMA16816(c, a, b0, b1) \
    asm volatile("mma.sync.aligned.m16n8k16.row.col.f32.f16.f16.f32 " \
        "{%0,%1,%2,%3}, {%4,%5,%6,%7}, {%8,%9}, {%0,%1,%2,%3};" \
        : "+f"((c)[0]), "+f"((c)[1]), "+f"((c)[2]), "+f"((c)[3]) \
        : "r"((a)[0]), "r"((a)[1]), "r"((a)[2]), "r"((a)[3]), "r"(b0), "r"(b1))
#define CP16(dst, src) \
    asm volatile("cp.async.cg.shared.global [%0], [%1], 16;" :: "r"(dst), "l"(src) : "memory")
#define CP_COMMIT()  asm volatile("cp.async.commit_group;" ::: "memory")
#define CP_WAIT1()   asm volatile("cp.async.wait_group 1;" ::: "memory")
#define CP_WAIT0()   asm volatile("cp.async.wait_group 0;" ::: "memory")

// ---------------- coefficient kernel ----------------
__global__ void coef_kernel(const float* __restrict__ a_pos, const float* __restrict__ b_pos,
                            const float* __restrict__ a_neg, const float* __restrict__ b_neg)
{
    int h = blockIdx.x;
    int d = threadIdx.x;
    bool neg = (blockIdx.y != 0);
    const float* A  = neg ? a_neg : a_pos;
    const float* Bm = neg ? b_neg : b_pos;
    float* CE = neg ? g_CEn : g_CE;
    float* CF = neg ? g_CFn : g_CF;

    __shared__ float sa[NKP][RANKC];
    for (int i = threadIdx.x; i < NKP * RANKC; i += 128)
        sa[i / RANKC][i % RANKC] = A[h * NKP * RANKC + i];
    __syncthreads();

    float br[RANKC];
#pragma unroll
    for (int r = 0; r < RANKC; r++)
        br[r] = Bm[((size_t)h * RANKC + r) * HDIM + d];

    float kind[NKP];
#pragma unroll
    for (int k = 0; k < NKP; k++) {
        float s = 0.f;
#pragma unroll
        for (int r = 0; r < RANKC; r++) s += sa[k][r] * br[r];
        kind[k] = s;
    }

    const float cm = 15.0f / 2046.0f;
    int c = h * HDIM + d;
    float Pp = 0.f, Qp = 0.f;
#pragma unroll
    for (int j = 0; j < NSEG; j++) {
        float D = kind[j + 1] - kind[j];
        float P = kind[j] - (cm + (float)j) * D;
        float Q = cm * D;
        int O = c_OFF[j];
        float gp = (float)pow((double)0.999, (double)O);
        CE[j * D1 + c] = gp * ((P - Pp) + (Q - Qp) * (float)O);
        CF[j * D1 + c] = gp * (Q - Qp);
        Pp = P; Qp = Q;
    }
}

// ---------------- x -> fp16 hi/lo ----------------
__global__ __launch_bounds__(256)
void convert_split_x(const float* __restrict__ src)
{
    __half* dh = g_xh;
    __half* dl = g_xl;
    int i = blockIdx.x * blockDim.x + threadIdx.x;
    float4 v = ((const float4*)src)[i];
    float vv[4] = {v.x, v.y, v.z, v.w};
    __half h[4], l[4];
#pragma unroll
    for (int j = 0; j < 4; j++) {
        h[j] = __float2half_rn(vv[j]);
        l[j] = __float2half_rn(vv[j] - __half2float(h[j]));
    }
    ((__half2*)dh)[2*i]   = __halves2half2(h[0], h[1]);
    ((__half2*)dh)[2*i+1] = __halves2half2(h[2], h[3]);
    ((__half2*)dl)[2*i]   = __halves2half2(l[0], l[1]);
    ((__half2*)dl)[2*i+1] = __halves2half2(l[2], l[3]);
}

// transpose fp32 weight [R][C] -> fp16 hi [C][R] (into g_Wth)
__global__ __launch_bounds__(256)
void transpose_w(const float* __restrict__ src, int R, int C)
{
    __half* dh = g_Wth;
    __shared__ float tile[32][33];
    int c0 = blockIdx.x * 32, r0 = blockIdx.y * 32;
    int tx = threadIdx.x & 31, ty = threadIdx.x >> 5;  // (32,8)
#pragma unroll
    for (int j = 0; j < 4; j++)
        tile[ty + 8 * j][tx] = src[(size_t)(r0 + ty + 8 * j) * C + c0 + tx];
    __syncthreads();
#pragma unroll
    for (int j = 0; j < 4; j++) {
        float v = tile[tx][ty + 8 * j];
        dh[(size_t)(c0 + ty + 8 * j) * R + r0 + tx] = __float2half_rn(v);
    }
}

// ---------------- GEMM 1/2: 2-pass, 128x64 tile, A m-major (R12 proven) ----------------
#define GM_KC    32
#define ST_AH    0
#define ST_AL    8192
#define ST_BH    16384
#define STAGE_SZ 20480
#define GEMM_SMEM (2 * STAGE_SZ)

__global__ __launch_bounds__(256, 3)
void gemm_f16_split(const float* __restrict__ bias, int Ktot, int c_sel)
{
    const __half* Ah = g_xh;
    const __half* Al = g_xl;
    const __half* Bh = g_Wth;
    float* Cout = c_sel ? g_Vt : g_Ut;
    const int strideC = RTOT;

    extern __shared__ char dsm[];
    uint32_t sbase = smem_to_u32(dsm);
    int tid = threadIdx.x;
    int wid = tid >> 5, lane = tid & 31;
    int m0 = blockIdx.x * 128, n0 = blockIdx.y * 64;
    int wm = wid & 1;
    int wn = wid >> 1;

    int a_r = (lane & 7) + ((lane >> 3) & 1) * 8;
    int a_c = (lane >> 4) * 16;
    int b_r = (lane & 7) + ((lane >> 4) & 1) * 8;
    int b_c = ((lane >> 3) & 1) * 16;

    float acc[4][2][4];
#pragma unroll
    for (int i = 0; i < 4; i++)
#pragma unroll
        for (int j = 0; j < 2; j++)
#pragma unroll
            for (int q = 0; q < 4; q++) acc[i][j][q] = 0.f;

    const __half* pAH = Ah + (size_t)m0 * Ktot;
    const __half* pAL = Al + (size_t)m0 * Ktot;
    const __half* pBH = Bh + (size_t)n0 * Ktot;

    int sa_row = tid >> 2, sa_seg = tid & 3;
    uint32_t sa_off  = SMEM_SW64((uint32_t)(sa_row * 64 + sa_seg * 16));
    uint32_t sa_off2 = SMEM_SW64((uint32_t)((sa_row + 64) * 64 + sa_seg * 16));

    int nkc = Ktot / GM_KC;

    auto load_chunk = [&](int kc, int s) {
        int k0 = kc * GM_KC;
        uint32_t st = sbase + s * STAGE_SZ;
        CP16(st + ST_AH + sa_off,  pAH + (size_t)sa_row * Ktot + k0 + sa_seg * 8);
        CP16(st + ST_AH + sa_off2, pAH + (size_t)(sa_row + 64) * Ktot + k0 + sa_seg * 8);
        CP16(st + ST_AL + sa_off,  pAL + (size_t)sa_row * Ktot + k0 + sa_seg * 8);
        CP16(st + ST_AL + sa_off2, pAL + (size_t)(sa_row + 64) * Ktot + k0 + sa_seg * 8);
        CP16(st + ST_BH + sa_off,  pBH + (size_t)sa_row * Ktot + k0 + sa_seg * 8);
    };

    load_chunk(0, 0);
    CP_COMMIT();

    for (int kc = 0; kc < nkc; kc++) {
        int s = kc & 1;
        if (kc + 1 < nkc) {
            load_chunk(kc + 1, s ^ 1);
            CP_COMMIT();
            CP_WAIT1();
        } else {
            CP_WAIT0();
        }
        __syncthreads();

        uint32_t st = sbase + s * STAGE_SZ;
#pragma unroll
        for (int ks = 0; ks < 2; ks++) {
            uint32_t aH[4][4], aL[4][4];
#pragma unroll
            for (int mt = 0; mt < 4; mt++) {
                int m = wm * 64 + mt * 16 + a_r;
                uint32_t off = SMEM_SW64((uint32_t)(m * 64 + ks * 32 + a_c));
                LDM4(aH[mt], st + ST_AH + off);
                LDM4(aL[mt], st + ST_AL + off);
            }
            uint32_t bH[4];
            {
                int n = wn * 16 + b_r;
                uint32_t off = SMEM_SW64((uint32_t)(n * 64 + ks * 32 + b_c));
                LDM4(bH, st + ST_BH + off);
            }
#pragma unroll
            for (int mt = 0; mt < 4; mt++) {
                MMA16816(acc[mt][0], aH[mt], bH[0], bH[1]);
                MMA16816(acc[mt][0], aL[mt], bH[0], bH[1]);
                MMA16816(acc[mt][1], aH[mt], bH[2], bH[3]);
                MMA16816(acc[mt][1], aL[mt], bH[2], bH[3]);
            }
        }
        __syncthreads();
    }

    int er = lane >> 2, ec = (lane & 3) * 2;
#pragma unroll
    for (int mt = 0; mt < 4; mt++) {
#pragma unroll
        for (int nt = 0; nt < 2; nt++) {
            int mA = m0 + wm * 64 + mt * 16 + er;
            int nA = n0 + wn * 16 + nt * 8 + ec;
            float b0 = bias[nA], b1 = bias[nA + 1];
            float* c = acc[mt][nt];
            Cout[(size_t)nA * strideC + mA]           = silu_f(c[0] + b0);
            Cout[(size_t)(nA + 1) * strideC + mA]     = silu_f(c[1] + b1);
            Cout[(size_t)nA * strideC + mA + 8]       = silu_f(c[2] + b0);
            Cout[(size_t)(nA + 1) * strideC + mA + 8] = silu_f(c[3] + b1);
        }
    }
}

// ---------------- GEMM 3: A k-major via ldmatrix.trans ----------------
__global__ __launch_bounds__(256, 3)
void gemm_f16_at(const float* __restrict__ bias, float* __restrict__ ext_out, int Ktot)
{
    const __half* Bh = g_Wth;
    extern __shared__ char dsm[];
    uint32_t sbase = smem_to_u32(dsm);
    int tid = threadIdx.x;
    int wid = tid >> 5, lane = tid & 31;
    int m0 = blockIdx.x * 128, n0 = blockIdx.y * 64;
    int wm = wid & 1;
    int wn = wid >> 1;

    int b_r = (lane & 7) + ((lane >> 4) & 1) * 8;
    int b_c = ((lane >> 3) & 1) * 16;
    int at_k8 = ((lane >> 4) & 1) * 8 + (lane & 7);
    int at_m8 = ((lane >> 3) & 1) * 8;

    float acc[4][2][4];
#pragma unroll
    for (int i = 0; i < 4; i++)
#pragma unroll
        for (int j = 0; j < 2; j++)
#pragma unroll
            for (int q = 0; q < 4; q++) acc[i][j][q] = 0.f;

    const __half* pBH = Bh + (size_t)n0 * Ktot;

    int sb_row = tid >> 2, sb_seg = tid & 3;
    uint32_t sb_off = SMEM_SW64((uint32_t)(sb_row * 64 + sb_seg * 16));
    int ar = tid >> 3, ag = tid & 7;
    uint32_t a_sw1 = (uint32_t)(ar * 256 + ((ag * 16) ^ ((ar & 7) * 16)));
    uint32_t a_sw2 = (uint32_t)(ar * 256 + (((ag + 8) * 16) ^ ((ar & 7) * 16)));

    int nkc = Ktot / GM_KC;

    auto load_chunk = [&](int kc, int s) {
        int k0 = kc * GM_KC;
        uint32_t st = sbase + s * STAGE_SZ;
        const __half* srcH = g_Ath + (size_t)(k0 + ar) * RTOT + m0;
        const __half* srcL = g_Atl + (size_t)(k0 + ar) * RTOT + m0;
        CP16(st + ST_AH + a_sw1, srcH + ag * 8);
        CP16(st + ST_AH + a_sw2, srcH + (ag + 8) * 8);
        CP16(st + ST_AL + a_sw1, srcL + ag * 8);
        CP16(st + ST_AL + a_sw2, srcL + (ag + 8) * 8);
        CP16(st + ST_BH + sb_off, pBH + (size_t)sb_row * Ktot + k0 + sb_seg * 8);
    };

    load_chunk(0, 0);
    CP_COMMIT();

    for (int kc = 0; kc < nkc; kc++) {
        int s = kc & 1;
        if (kc + 1 < nkc) {
            load_chunk(kc + 1, s ^ 1);
            CP_COMMIT();
            CP_WAIT1();
        } else {
            CP_WAIT0();
        }
        __syncthreads();

        uint32_t st = sbase + s * STAGE_SZ;
#pragma unroll
        for (int ks = 0; ks < 2; ks++) {
            int k_row = ks * 16 + at_k8;
            uint32_t krow_base = (uint32_t)(k_row * 256);
            uint32_t kxor = (uint32_t)((k_row & 7) * 16);
            uint32_t aH[4][4], aL[4][4];
#pragma unroll
            for (int mt = 0; mt < 4; mt++) {
                int moff = wm * 64 + mt * 16 + at_m8;
                uint32_t off = krow_base + (((uint32_t)(moff * 2)) ^ kxor);
                LDM4T(aH[mt], st + ST_AH + off);
                LDM4T(aL[mt], st + ST_AL + off);
            }
            uint32_t bH[4];
            {
                int n = wn * 16 + b_r;
                uint32_t off = SMEM_SW64((uint32_t)(n * 64 + ks * 32 + b_c));
                LDM4(bH, st + ST_BH + off);
            }
#pragma unroll
            for (int mt = 0; mt < 4; mt++) {
                MMA16816(acc[mt][0], aH[mt], bH[0], bH[1]);
                MMA16816(acc[mt][0], aL[mt], bH[0], bH[1]);
                MMA16816(acc[mt][1], aH[mt], bH[2], bH[3]);
                MMA16816(acc[mt][1], aL[mt], bH[2], bH[3]);
            }
        }
        __syncthreads();
    }

    int er = lane >> 2, ec = (lane & 3) * 2;
#pragma unroll
    for (int mt = 0; mt < 4; mt++) {
#pragma unroll
        for (int nt = 0; nt < 2; nt++) {
            int mA = m0 + wm * 64 + mt * 16 + er;
            int nA = n0 + wn * 16 + nt * 8 + ec;
            float b0 = bias[nA], b1 = bias[nA + 1];
            float* c = acc[mt][nt];
            ext_out[(size_t)mA * DMODEL + nA]           = c[0] + b0;
            ext_out[(size_t)mA * DMODEL + nA + 1]       = c[1] + b1;
            ext_out[(size_t)(mA + 8) * DMODEL + nA]     = c[2] + b0;
            ext_out[(size_t)(mA + 8) * DMODEL + nA + 1] = c[3] + b1;
        }
    }
}

// ---------------- fused scan + combine (float2-packed scan outputs) ----------------
__device__ void scan_pass2(const float* sv, float* sa, float* sk, float* sp, float* sq,
                           float2* oef, int tid, bool rev)
{
    float vloc[8];
    int base = tid * 8;
#pragma unroll
    for (int i = 0; i < 8; i++)
        vloc[i] = sv[rev ? (SEQ - 1 - (base + i)) : (base + i)];

    float e = 0.f, f = 0.f;
#pragma unroll
    for (int i = 0; i < 8; i++) { f = GAMMA_F * (f + e); e = GAMMA_F * e + vloc[i]; }
    sa[tid] = G8; sk[tid] = 8.f; sp[tid] = e; sq[tid] = f;
    __syncthreads();

    for (int d = 1; d < 256; d <<= 1) {
        float pa = 0.f, pk = 0.f, pp = 0.f, pq = 0.f;
        bool has = tid >= d;
        if (has) { pa = sa[tid - d]; pk = sk[tid - d]; pp = sp[tid - d]; pq = sq[tid - d]; }
        float ca = sa[tid], ck = sk[tid], cp = sp[tid], cq = sq[tid];
        __syncthreads();
        if (has) {
            sp[tid] = ca * pp + cp;
            sq[tid] = ca * pq + ca * ck * pp + cq;
            sa[tid] = pa * ca;
            sk[tid] = pk + ck;
        }
        __syncthreads();
    }
    float E0 = tid ? sp[tid - 1] : 0.f;
    float F0 = tid ? sq[tid - 1] : 0.f;
    e = E0; f = F0;
#pragma unroll
    for (int i = 0; i < 8; i++) {
        float fn = GAMMA_F * (f + e);
        e = GAMMA_F * e + vloc[i];
        f = fn;
        int t = base + i;
        int o = rev ? (SEQ - 1 - t) : t;
        oef[o] = make_float2(e, f);
    }
    __syncthreads();
}

__global__ __launch_bounds__(256)
void scan_combine_kernel(const float* __restrict__ t_zero)
{
    int c = blockIdx.x >> 1;
    int b = blockIdx.x & 1;
    size_t base = (size_t)c * RTOT + (size_t)b * SEQ;

    __shared__ float sv[SEQ];
    __shared__ float2 sef[SEQ], sgh[SEQ];
    __shared__ float sa[256], sk[256], sp[256], sq[256];
    __shared__ float sCE[NSEG], sCF[NSEG], sCEn[NSEG], sCFn[NSEG];
    int tid = threadIdx.x;
    const float4* vin = (const float4*)(g_Vt + base);
    for (int i = tid; i < SEQ / 4; i += 256) ((float4*)sv)[i] = vin[i];
    if (tid < NSEG) {
        sCE [tid] = g_CE [tid * D1 + c];
        sCF [tid] = g_CF [tid * D1 + c];
        sCEn[tid] = g_CEn[tid * D1 + c];
        sCFn[tid] = g_CFn[tid * D1 + c];
    }
    float tz = t_zero[c];
    __syncthreads();

    scan_pass2(sv, sa, sk, sp, sq, sef, tid, false);
    scan_pass2(sv, sa, sk, sp, sq, sgh, tid, true);

#pragma unroll
    for (int rpt = 0; rpt < 8; rpt++) {
        int t = tid + rpt * 256;
        float acc = tz * sv[t];
#pragma unroll
        for (int m = 0; m < NSEG; m++) {
            int o = c_OFF[m];
            int tm = t - o;
            if (tm >= 0)  { float2 ef = sef[tm]; acc += sCE[m]  * ef.x + sCF[m]  * ef.y; }
            int tp = t + o;
            if (tp < SEQ) { float2 gh = sgh[tp]; acc += sCEn[m] * gh.x + sCFn[m] * gh.y; }
        }
        float val = acc * g_Ut[base + t];
        __half h = __float2half_rn(val);
        g_Ath[base + t] = h;
        g_Atl[base + t] = __float2half_rn(val - __half2float(h));
    }
}

// ---------------- launch ----------------
extern "C" void kernel_launch(void* const* d_in, const int* in_sizes, int n_in,
                              void* d_out, int out_size)
{
    (void)in_sizes; (void)n_in; (void)out_size;
    const float* x      = (const float*)d_in[0];
    const float* Wu     = (const float*)d_in[1];
    const float* bu     = (const float*)d_in[2];
    const float* Wv     = (const float*)d_in[3];
    const float* bv     = (const float*)d_in[4];
    const float* Wo     = (const float*)d_in[5];
    const float* bo     = (const float*)d_in[6];
    const float* a_pos  = (const float*)d_in[7];
    const float* b_pos  = (const float*)d_in[8];
    const float* a_neg  = (const float*)d_in[9];
    const float* b_neg  = (const float*)d_in[10];
    const float* t_zero = (const float*)d_in[11];
    float* out = (float*)d_out;

    coef_kernel<<<dim3(NHEAD, 2), 128>>>(a_pos, b_pos, a_neg, b_neg);

    // x -> fp16 hi/lo planes
    convert_split_x<<<RTOT * DMODEL / 4 / 256, 256>>>(x);

    dim3 g12(RTOT / 128, D1 / 64);
    dim3 g3(RTOT / 128, DMODEL / 64);

    // GEMM1: U^T = silu(x @ Wu + bu)^T
    transpose_w<<<dim3(D1 / 32, DMODEL / 32), 256>>>(Wu, DMODEL, D1);
    gemm_f16_split<<<g12, 256, GEMM_SMEM>>>(bu, DMODEL, 0);

    // GEMM2: V^T = silu(x @ Wv + bv)^T
    transpose_w<<<dim3(D1 / 32, DMODEL / 32), 256>>>(Wv, DMODEL, D1);
    gemm_f16_split<<<g12, 256, GEMM_SMEM>>>(bv, DMODEL, 1);

    // fused scans + combine -> fp16 hi/lo planes [k][m]
    scan_combine_kernel<<<D1 * BATCH, 256>>>(t_zero);

    // Wo [k][n] -> [n][k] fp16
    transpose_w<<<dim3(DMODEL / 32, D1 / 32), 256>>>(Wo, D1, DMODEL);

    // GEMM3: out = Gt^T @ Wo + bo  (A via ldmatrix.trans)
    gemm_f16_at<<<g3, 256, GEMM_SMEM>>>(bo, out, D1);
}

// round 16
// speedup vs baseline: 2.1541x; 1.3182x over previous
#include <cuda_runtime.h>
#include <cuda_fp16.h>
#include <cstdint>
#include <math.h>

// ---------------- problem constants ----------------
#define SEQ     2048
#define BATCH   2
#define RTOT    4096      // BATCH*SEQ
#define DMODEL  1024
#define D1      2048
#define NHEAD   16
#define HDIM    128
#define NKP     16
#define RANKC   32
#define GAMMA_F 0.999f
#define NSEG    15

__device__ __constant__ float G8 =
    (float)(0.999*0.999*0.999*0.999*0.999*0.999*0.999*0.999);
__constant__ int c_OFF[NSEG] = {1,138,274,411,547,683,820,956,1093,1229,1365,1502,1638,1775,1911};

// ---------------- device-global scratch (NEVER passed from host) ----------------
__device__ __align__(128) float g_Ut[(size_t)D1 * RTOT]; // U^T  [c][m]
__device__ __align__(128) float g_Vt[(size_t)D1 * RTOT]; // V^T  [c][m]
__device__ __align__(128) float g_CE [NSEG * D1];
__device__ __align__(128) float g_CF [NSEG * D1];
__device__ __align__(128) float g_CEn[NSEG * D1];
__device__ __align__(128) float g_CFn[NSEG * D1];
// fp16 planes (single precision-pass)
__device__ __align__(128) __half g_xh [(size_t)RTOT * DMODEL];
__device__ __align__(128) __half g_Wth[(size_t)D1 * DMODEL];
__device__ __align__(128) __half g_Ath[(size_t)D1 * RTOT];  // gated, [k][m]

// ---------------- helpers ----------------
__device__ __forceinline__ uint32_t smem_to_u32(const void* p) {
    uint32_t a;
    asm("{ .reg .u64 t; cvta.to.shared.u64 t, %1; cvt.u32.u64 %0, t; }" : "=r"(a) : "l"(p));
    return a;
}
#define SMEM_SW64(o) ((o) ^ (((o) >> 3) & 0x30))
__device__ __forceinline__ float silu_f(float x) { return x / (1.0f + expf(-x)); }

#define LDM4(r, addr) \
    asm volatile("ldmatrix.sync.aligned.m8n8.x4.shared.b16 {%0,%1,%2,%3}, [%4];" \
        : "=r"((r)[0]), "=r"((r)[1]), "=r"((r)[2]), "=r"((r)[3]) : "r"(addr))
#define LDM4T(r, addr) \
    asm volatile("ldmatrix.sync.aligned.m8n8.x4.trans.shared.b16 {%0,%1,%2,%3}, [%4];" \
        : "=r"((r)[0]), "=r"((r)[1]), "=r"((r)[2]), "=r"((r)[3]) : "r"(addr))
#define MMA16816(c, a, b0, b1) \
    asm volatile("mma.sync.aligned.m16n8k16.row.col.f32.f16.f16.f32 " \
        "{%0,%1,%2,%3}, {%4,%5,%6,%7}, {%8,%9}, {%0,%1,%2,%3};" \
        : "+f"((c)[0]), "+f"((c)[1]), "+f"((c)[2]), "+f"((c)[3]) \
        : "r"((a)[0]), "r"((a)[1]), "r"((a)[2]), "r"((a)[3]), "r"(b0), "r"(b1))
#define CP16(dst, src) \
    asm volatile("cp.async.cg.shared.global [%0], [%1], 16;" :: "r"(dst), "l"(src) : "memory")
#define CP_COMMIT()  asm volatile("cp.async.commit_group;" ::: "memory")
#define CP_WAIT1()   asm volatile("cp.async.wait_group 1;" ::: "memory")
#define CP_WAIT0()   asm volatile("cp.async.wait_group 0;" ::: "memory")

// ---------------- coefficient kernel ----------------
__global__ void coef_kernel(const float* __restrict__ a_pos, const float* __restrict__ b_pos,
                            const float* __restrict__ a_neg, const float* __restrict__ b_neg)
{
    int h = blockIdx.x;
    int d = threadIdx.x;
    bool neg = (blockIdx.y != 0);
    const float* A  = neg ? a_neg : a_pos;
    const float* Bm = neg ? b_neg : b_pos;
    float* CE = neg ? g_CEn : g_CE;
    float* CF = neg ? g_CFn : g_CF;

    __shared__ float sa[NKP][RANKC];
    for (int i = threadIdx.x; i < NKP * RANKC; i += 128)
        sa[i / RANKC][i % RANKC] = A[h * NKP * RANKC + i];
    __syncthreads();

    float br[RANKC];
#pragma unroll
    for (int r = 0; r < RANKC; r++)
        br[r] = Bm[((size_t)h * RANKC + r) * HDIM + d];

    float kind[NKP];
#pragma unroll
    for (int k = 0; k < NKP; k++) {
        float s = 0.f;
#pragma unroll
        for (int r = 0; r < RANKC; r++) s += sa[k][r] * br[r];
        kind[k] = s;
    }

    const float cm = 15.0f / 2046.0f;
    int c = h * HDIM + d;
    float Pp = 0.f, Qp = 0.f;
#pragma unroll
    for (int j = 0; j < NSEG; j++) {
        float D = kind[j + 1] - kind[j];
        float P = kind[j] - (cm + (float)j) * D;
        float Q = cm * D;
        int O = c_OFF[j];
        float gp = (float)pow((double)0.999, (double)O);
        CE[j * D1 + c] = gp * ((P - Pp) + (Q - Qp) * (float)O);
        CF[j * D1 + c] = gp * (Q - Qp);
        Pp = P; Qp = Q;
    }
}

// ---------------- x -> fp16 ----------------
__global__ __launch_bounds__(256)
void convert_x(const float* __restrict__ src)
{
    __half* dh = g_xh;
    int i = blockIdx.x * blockDim.x + threadIdx.x;
    float4 v = ((const float4*)src)[i];
    ((__half2*)dh)[2*i]   = __halves2half2(__float2half_rn(v.x), __float2half_rn(v.y));
    ((__half2*)dh)[2*i+1] = __halves2half2(__float2half_rn(v.z), __float2half_rn(v.w));
}

// transpose fp32 weight [R][C] -> fp16 [C][R] (into g_Wth)
__global__ __launch_bounds__(256)
void transpose_w(const float* __restrict__ src, int R, int C)
{
    __half* dh = g_Wth;
    __shared__ float tile[32][33];
    int c0 = blockIdx.x * 32, r0 = blockIdx.y * 32;
    int tx = threadIdx.x & 31, ty = threadIdx.x >> 5;  // (32,8)
#pragma unroll
    for (int j = 0; j < 4; j++)
        tile[ty + 8 * j][tx] = src[(size_t)(r0 + ty + 8 * j) * C + c0 + tx];
    __syncthreads();
#pragma unroll
    for (int j = 0; j < 4; j++) {
        float v = tile[tx][ty + 8 * j];
        dh[(size_t)(c0 + ty + 8 * j) * R + r0 + tx] = __float2half_rn(v);
    }
}

// ---------------- GEMM 1/2: single-pass fp16, 128x64 tile, A m-major ----------------
#define GM_KC    32
#define ST_AH    0
#define ST_BH    8192
#define STAGE_SZ 12288
#define GEMM_SMEM (2 * STAGE_SZ)

__global__ __launch_bounds__(256, 3)
void gemm_f16(const float* __restrict__ bias, int Ktot, int c_sel)
{
    const __half* Ah = g_xh;
    const __half* Bh = g_Wth;
    float* Cout = c_sel ? g_Vt : g_Ut;
    const int strideC = RTOT;

    extern __shared__ char dsm[];
    uint32_t sbase = smem_to_u32(dsm);
    int tid = threadIdx.x;
    int wid = tid >> 5, lane = tid & 31;
    int m0 = blockIdx.x * 128, n0 = blockIdx.y * 64;
    int wm = wid & 1;
    int wn = wid >> 1;

    int a_r = (lane & 7) + ((lane >> 3) & 1) * 8;
    int a_c = (lane >> 4) * 16;
    int b_r = (lane & 7) + ((lane >> 4) & 1) * 8;
    int b_c = ((lane >> 3) & 1) * 16;

    float acc[4][2][4];
#pragma unroll
    for (int i = 0; i < 4; i++)
#pragma unroll
        for (int j = 0; j < 2; j++)
#pragma unroll
            for (int q = 0; q < 4; q++) acc[i][j][q] = 0.f;

    const __half* pAH = Ah + (size_t)m0 * Ktot;
    const __half* pBH = Bh + (size_t)n0 * Ktot;

    int sa_row = tid >> 2, sa_seg = tid & 3;
    uint32_t sa_off  = SMEM_SW64((uint32_t)(sa_row * 64 + sa_seg * 16));
    uint32_t sa_off2 = SMEM_SW64((uint32_t)((sa_row + 64) * 64 + sa_seg * 16));

    int nkc = Ktot / GM_KC;

    auto load_chunk = [&](int kc, int s) {
        int k0 = kc * GM_KC;
        uint32_t st = sbase + s * STAGE_SZ;
        CP16(st + ST_AH + sa_off,  pAH + (size_t)sa_row * Ktot + k0 + sa_seg * 8);
        CP16(st + ST_AH + sa_off2, pAH + (size_t)(sa_row + 64) * Ktot + k0 + sa_seg * 8);
        CP16(st + ST_BH + sa_off,  pBH + (size_t)sa_row * Ktot + k0 + sa_seg * 8);
    };

    load_chunk(0, 0);
    CP_COMMIT();

    for (int kc = 0; kc < nkc; kc++) {
        int s = kc & 1;
        if (kc + 1 < nkc) {
            load_chunk(kc + 1, s ^ 1);
            CP_COMMIT();
            CP_WAIT1();
        } else {
            CP_WAIT0();
        }
        __syncthreads();

        uint32_t st = sbase + s * STAGE_SZ;
#pragma unroll
        for (int ks = 0; ks < 2; ks++) {
            uint32_t aH[4][4];
#pragma unroll
            for (int mt = 0; mt < 4; mt++) {
                int m = wm * 64 + mt * 16 + a_r;
                uint32_t off = SMEM_SW64((uint32_t)(m * 64 + ks * 32 + a_c));
                LDM4(aH[mt], st + ST_AH + off);
            }
            uint32_t bH[4];
            {
                int n = wn * 16 + b_r;
                uint32_t off = SMEM_SW64((uint32_t)(n * 64 + ks * 32 + b_c));
                LDM4(bH, st + ST_BH + off);
            }
#pragma unroll
            for (int mt = 0; mt < 4; mt++) {
                MMA16816(acc[mt][0], aH[mt], bH[0], bH[1]);
                MMA16816(acc[mt][1], aH[mt], bH[2], bH[3]);
            }
        }
        __syncthreads();
    }

    int er = lane >> 2, ec = (lane & 3) * 2;
#pragma unroll
    for (int mt = 0; mt < 4; mt++) {
#pragma unroll
        for (int nt = 0; nt < 2; nt++) {
            int mA = m0 + wm * 64 + mt * 16 + er;
            int nA = n0 + wn * 16 + nt * 8 + ec;
            float b0 = bias[nA], b1 = bias[nA + 1];
            float* c = acc[mt][nt];
            Cout[(size_t)nA * strideC + mA]           = silu_f(c[0] + b0);
            Cout[(size_t)(nA + 1) * strideC + mA]     = silu_f(c[1] + b1);
            Cout[(size_t)nA * strideC + mA + 8]       = silu_f(c[2] + b0);
            Cout[(size_t)(nA + 1) * strideC + mA + 8] = silu_f(c[3] + b1);
        }
    }
}

// ---------------- GEMM 3: single-pass, A k-major via ldmatrix.trans ----------------
__global__ __launch_bounds__(256, 3)
void gemm_f16_at(const float* __restrict__ bias, float* __restrict__ ext_out, int Ktot)
{
    const __half* Bh = g_Wth;
    extern __shared__ char dsm[];
    uint32_t sbase = smem_to_u32(dsm);
    int tid = threadIdx.x;
    int wid = tid >> 5, lane = tid & 31;
    int m0 = blockIdx.x * 128, n0 = blockIdx.y * 64;
    int wm = wid & 1;
    int wn = wid >> 1;

    int b_r = (lane & 7) + ((lane >> 4) & 1) * 8;
    int b_c = ((lane >> 3) & 1) * 16;
    int at_k8 = ((lane >> 4) & 1) * 8 + (lane & 7);
    int at_m8 = ((lane >> 3) & 1) * 8;

    float acc[4][2][4];
#pragma unroll
    for (int i = 0; i < 4; i++)
#pragma unroll
        for (int j = 0; j < 2; j++)
#pragma unroll
            for (int q = 0; q < 4; q++) acc[i][j][q] = 0.f;

    const __half* pBH = Bh + (size_t)n0 * Ktot;

    int sb_row = tid >> 2, sb_seg = tid & 3;
    uint32_t sb_off = SMEM_SW64((uint32_t)(sb_row * 64 + sb_seg * 16));
    int ar = tid >> 3, ag = tid & 7;
    uint32_t a_sw1 = (uint32_t)(ar * 256 + ((ag * 16) ^ ((ar & 7) * 16)));
    uint32_t a_sw2 = (uint32_t)(ar * 256 + (((ag + 8) * 16) ^ ((ar & 7) * 16)));

    int nkc = Ktot / GM_KC;

    auto load_chunk = [&](int kc, int s) {
        int k0 = kc * GM_KC;
        uint32_t st = sbase + s * STAGE_SZ;
        const __half* srcH = g_Ath + (size_t)(k0 + ar) * RTOT + m0;
        CP16(st + ST_AH + a_sw1, srcH + ag * 8);
        CP16(st + ST_AH + a_sw2, srcH + (ag + 8) * 8);
        CP16(st + ST_BH + sb_off, pBH + (size_t)sb_row * Ktot + k0 + sb_seg * 8);
    };

    load_chunk(0, 0);
    CP_COMMIT();

    for (int kc = 0; kc < nkc; kc++) {
        int s = kc & 1;
        if (kc + 1 < nkc) {
            load_chunk(kc + 1, s ^ 1);
            CP_COMMIT();
            CP_WAIT1();
        } else {
            CP_WAIT0();
        }
        __syncthreads();

        uint32_t st = sbase + s * STAGE_SZ;
#pragma unroll
        for (int ks = 0; ks < 2; ks++) {
            int k_row = ks * 16 + at_k8;
            uint32_t krow_base = (uint32_t)(k_row * 256);
            uint32_t kxor = (uint32_t)((k_row & 7) * 16);
            uint32_t aH[4][4];
#pragma unroll
            for (int mt = 0; mt < 4; mt++) {
                int moff = wm * 64 + mt * 16 + at_m8;
                uint32_t off = krow_base + (((uint32_t)(moff * 2)) ^ kxor);
                LDM4T(aH[mt], st + ST_AH + off);
            }
            uint32_t bH[4];
            {
                int n = wn * 16 + b_r;
                uint32_t off = SMEM_SW64((uint32_t)(n * 64 + ks * 32 + b_c));
                LDM4(bH, st + ST_BH + off);
            }
#pragma unroll
            for (int mt = 0; mt < 4; mt++) {
                MMA16816(acc[mt][0], aH[mt], bH[0], bH[1]);
                MMA16816(acc[mt][1], aH[mt], bH[2], bH[3]);
            }
        }
        __syncthreads();
    }

    int er = lane >> 2, ec = (lane & 3) * 2;
#pragma unroll
    for (int mt = 0; mt < 4; mt++) {
#pragma unroll
        for (int nt = 0; nt < 2; nt++) {
            int mA = m0 + wm * 64 + mt * 16 + er;
            int nA = n0 + wn * 16 + nt * 8 + ec;
            float b0 = bias[nA], b1 = bias[nA + 1];
            float* c = acc[mt][nt];
            ext_out[(size_t)mA * DMODEL + nA]           = c[0] + b0;
            ext_out[(size_t)mA * DMODEL + nA + 1]       = c[1] + b1;
            ext_out[(size_t)(mA + 8) * DMODEL + nA]     = c[2] + b0;
            ext_out[(size_t)(mA + 8) * DMODEL + nA + 1] = c[3] + b1;
        }
    }
}

// ---------------- fused scan + combine (float2-packed scan outputs) ----------------
__device__ void scan_pass2(const float* sv, float* sa, float* sk, float* sp, float* sq,
                           float2* oef, int tid, bool rev)
{
    float vloc[8];
    int base = tid * 8;
#pragma unroll
    for (int i = 0; i < 8; i++)
        vloc[i] = sv[rev ? (SEQ - 1 - (base + i)) : (base + i)];

    float e = 0.f, f = 0.f;
#pragma unroll
    for (int i = 0; i < 8; i++) { f = GAMMA_F * (f + e); e = GAMMA_F * e + vloc[i]; }
    sa[tid] = G8; sk[tid] = 8.f; sp[tid] = e; sq[tid] = f;
    __syncthreads();

    for (int d = 1; d < 256; d <<= 1) {
        float pa = 0.f, pk = 0.f, pp = 0.f, pq = 0.f;
        bool has = tid >= d;
        if (has) { pa = sa[tid - d]; pk = sk[tid - d]; pp = sp[tid - d]; pq = sq[tid - d]; }
        float ca = sa[tid], ck = sk[tid], cp = sp[tid], cq = sq[tid];
        __syncthreads();
        if (has) {
            sp[tid] = ca * pp + cp;
            sq[tid] = ca * pq + ca * ck * pp + cq;
            sa[tid] = pa * ca;
            sk[tid] = pk + ck;
        }
        __syncthreads();
    }
    float E0 = tid ? sp[tid - 1] : 0.f;
    float F0 = tid ? sq[tid - 1] : 0.f;
    e = E0; f = F0;
#pragma unroll
    for (int i = 0; i < 8; i++) {
        float fn = GAMMA_F * (f + e);
        e = GAMMA_F * e + vloc[i];
        f = fn;
        int t = base + i;
        int o = rev ? (SEQ - 1 - t) : t;
        oef[o] = make_float2(e, f);
    }
    __syncthreads();
}

__global__ __launch_bounds__(256)
void scan_combine_kernel(const float* __restrict__ t_zero)
{
    int c = blockIdx.x >> 1;
    int b = blockIdx.x & 1;
    size_t base = (size_t)c * RTOT + (size_t)b * SEQ;

    __shared__ float sv[SEQ];
    __shared__ float2 sef[SEQ], sgh[SEQ];
    __shared__ float sa[256], sk[256], sp[256], sq[256];
    __shared__ float sCE[NSEG], sCF[NSEG], sCEn[NSEG], sCFn[NSEG];
    int tid = threadIdx.x;
    const float4* vin = (const float4*)(g_Vt + base);
    for (int i = tid; i < SEQ / 4; i += 256) ((float4*)sv)[i] = vin[i];
    if (tid < NSEG) {
        sCE [tid] = g_CE [tid * D1 + c];
        sCF [tid] = g_CF [tid * D1 + c];
        sCEn[tid] = g_CEn[tid * D1 + c];
        sCFn[tid] = g_CFn[tid * D1 + c];
    }
    float tz = t_zero[c];
    __syncthreads();

    scan_pass2(sv, sa, sk, sp, sq, sef, tid, false);
    scan_pass2(sv, sa, sk, sp, sq, sgh, tid, true);

#pragma unroll
    for (int rpt = 0; rpt < 8; rpt++) {
        int t = tid + rpt * 256;
        float acc = tz * sv[t];
#pragma unroll
        for (int m = 0; m < NSEG; m++) {
            int o = c_OFF[m];
            int tm = t - o;
            if (tm >= 0)  { float2 ef = sef[tm]; acc += sCE[m]  * ef.x + sCF[m]  * ef.y; }
            int tp = t + o;
            if (tp < SEQ) { float2 gh = sgh[tp]; acc += sCEn[m] * gh.x + sCFn[m] * gh.y; }
        }
        float val = acc * g_Ut[base + t];
        g_Ath[base + t] = __float2half_rn(val);
    }
}

// ---------------- launch ----------------
extern "C" void kernel_launch(void* const* d_in, const int* in_sizes, int n_in,
                              void* d_out, int out_size)
{
    (void)in_sizes; (void)n_in; (void)out_size;
    const float* x      = (const float*)d_in[0];
    const float* Wu     = (const float*)d_in[1];
    const float* bu     = (const float*)d_in[2];
    const float* Wv     = (const float*)d_in[3];
    const float* bv     = (const float*)d_in[4];
    const float* Wo     = (const float*)d_in[5];
    const float* bo     = (const float*)d_in[6];
    const float* a_pos  = (const float*)d_in[7];
    const float* b_pos  = (const float*)d_in[8];
    const float* a_neg  = (const float*)d_in[9];
    const float* b_neg  = (const float*)d_in[10];
    const float* t_zero = (const float*)d_in[11];
    float* out = (float*)d_out;

    coef_kernel<<<dim3(NHEAD, 2), 128>>>(a_pos, b_pos, a_neg, b_neg);

    // x -> fp16
    convert_x<<<RTOT * DMODEL / 4 / 256, 256>>>(x);

    dim3 g12(RTOT / 128, D1 / 64);
    dim3 g3(RTOT / 128, DMODEL / 64);

    // GEMM1: U^T = silu(x @ Wu + bu)^T
    transpose_w<<<dim3(D1 / 32, DMODEL / 32), 256>>>(Wu, DMODEL, D1);
    gemm_f16<<<g12, 256, GEMM_SMEM>>>(bu, DMODEL, 0);

    // GEMM2: V^T = silu(x @ Wv + bv)^T
    transpose_w<<<dim3(D1 / 32, DMODEL / 32), 256>>>(Wv, DMODEL, D1);
    gemm_f16<<<g12, 256, GEMM_SMEM>>>(bv, DMODEL, 1);

    // fused scans + combine -> fp16 [k][m]
    scan_combine_kernel<<<D1 * BATCH, 256>>>(t_zero);

    // Wo [k][n] -> [n][k] fp16
    transpose_w<<<dim3(DMODEL / 32, D1 / 32), 256>>>(Wo, D1, DMODEL);

    // GEMM3: out = Gt^T @ Wo + bo  (A via ldmatrix.trans)
    gemm_f16_at<<<g3, 256, GEMM_SMEM>>>(bo, out, D1);
}